// round 2
// baseline (speedup 1.0000x reference)
#include <cuda_runtime.h>

#define BB 4
#define SS 4096
#define HH 1024
#define DD 64
#define NEG_INF_F (-1.0e12f)

// Scratch for K, Q, V projections: 3 x [B*S, D] fp32 = 12 MB
__device__ float g_KQV[3][BB * SS * DD];

// ---------------------------------------------------------------------------
// Fused projection: for each row m of x [16384 x 1024], compute
//   K[m] = x[m] @ Wk^T, Q[m] = x[m] @ Wq^T, V[m] = x[m] @ Wv^T
// BM=64 rows, BN=192 (all three outputs), BK=16. 256 threads, 4x12 microtile.
// ---------------------------------------------------------------------------
__global__ void proj_kernel(const float* __restrict__ x,
                            const float* __restrict__ Wk,
                            const float* __restrict__ Wq,
                            const float* __restrict__ Wv) {
    __shared__ float Xs[64][17];
    __shared__ float Ws[192][17];

    const int tid = threadIdx.x;
    const int ty = tid >> 4;          // 0..15 -> 4 rows each
    const int tx = tid & 15;          // 0..15 -> 12 cols each (strided by 16)
    const int m0 = blockIdx.x * 64;

    float acc[4][12];
#pragma unroll
    for (int i = 0; i < 4; i++)
#pragma unroll
        for (int j = 0; j < 12; j++) acc[i][j] = 0.0f;

    for (int k0 = 0; k0 < HH; k0 += 16) {
        // Load Xs: 64x16 = 1024 elems, 4 per thread
#pragma unroll
        for (int i = 0; i < 4; i++) {
            int idx = tid + i * 256;
            int r = idx >> 4, c = idx & 15;
            Xs[r][c] = x[(size_t)(m0 + r) * HH + k0 + c];
        }
        // Load Ws: 192x16 = 3072 elems, 12 per thread. Rows 0..63 = Wk,
        // 64..127 = Wq, 128..191 = Wv.
#pragma unroll
        for (int i = 0; i < 12; i++) {
            int idx = tid + i * 256;
            int r = idx >> 4, c = idx & 15;
            const float* W = (r < 64) ? Wk : ((r < 128) ? Wq : Wv);
            int rr = r & 63;
            Ws[r][c] = W[(size_t)rr * HH + k0 + c];
        }
        __syncthreads();

#pragma unroll
        for (int kk = 0; kk < 16; kk++) {
            float a[4], b[12];
#pragma unroll
            for (int i = 0; i < 4; i++) a[i] = Xs[ty * 4 + i][kk];
#pragma unroll
            for (int j = 0; j < 12; j++) b[j] = Ws[tx + 16 * j][kk];
#pragma unroll
            for (int i = 0; i < 4; i++)
#pragma unroll
                for (int j = 0; j < 12; j++) acc[i][j] += a[i] * b[j];
        }
        __syncthreads();
    }

#pragma unroll
    for (int j = 0; j < 12; j++) {
        int n = tx + 16 * j;          // 0..191
        float* out = g_KQV[n >> 6];
        int d = n & 63;
#pragma unroll
        for (int i = 0; i < 4; i++)
            out[(size_t)(m0 + 4 * ty + i) * DD + d] = acc[i][j];
    }
}

// ---------------------------------------------------------------------------
// Flash-style attention with swapped roles:
//   out[b,s,:] = softmax_t( scale * K[b,s]·Q[b,t] , mask on t ) @ V[b,t,:]
// Block: 64 K-rows, loop over t in blocks of 64. 256 threads.
// Phase 1 thread map: rows 4*ty+i, cols tx+16*j (conflict-friendly).
// Phase 2 thread map: rows 4*ty+i, d-cols 4*tx+j (float4 V loads).
// Shared stride 68 floats: 16B-aligned rows, 2-way-max bank conflicts.
// ---------------------------------------------------------------------------
#define LDS 68

__global__ void attn_kernel(const int* __restrict__ mask,
                            float* __restrict__ out) {
    extern __shared__ float sm[];
    float* Ks = sm;                    // 64 * LDS
    float* Qs = Ks + 64 * LDS;
    float* Vs = Qs + 64 * LDS;
    float* Ps = Vs + 64 * LDS;
    int* ms = (int*)(Ps + 64 * LDS);   // 64 ints

    const int b = blockIdx.y;
    const int r0 = blockIdx.x * 64;
    const float* K = g_KQV[0] + (size_t)b * SS * DD;
    const float* Q = g_KQV[1] + (size_t)b * SS * DD;
    const float* V = g_KQV[2] + (size_t)b * SS * DD;

    const int tid = threadIdx.x;
    const int ty = tid >> 4;
    const int tx = tid & 15;
    const float scale = 0.125f;        // 1/sqrt(64)

    // Load K block once
    for (int i = tid; i < 64 * 64; i += 256) {
        int r = i >> 6, c = i & 63;
        Ks[r * LDS + c] = K[(size_t)(r0 + r) * DD + c];
    }

    float m_i[4], l_i[4], O[4][4];
#pragma unroll
    for (int i = 0; i < 4; i++) {
        m_i[i] = -1e30f;
        l_i[i] = 0.0f;
#pragma unroll
        for (int j = 0; j < 4; j++) O[i][j] = 0.0f;
    }

    for (int t0 = 0; t0 < SS; t0 += 64) {
        __syncthreads();               // prev phase-2 done (and Ks load on iter 0)
        for (int i = tid; i < 64 * 64; i += 256) {
            int r = i >> 6, c = i & 63;
            Qs[r * LDS + c] = Q[(size_t)(t0 + r) * DD + c];
            Vs[r * LDS + c] = V[(size_t)(t0 + r) * DD + c];
        }
        if (tid < 64) ms[tid] = mask[b * SS + t0 + tid];
        __syncthreads();

        // Phase 1: sv[i][j] = K[r0+4ty+i] . Q[t0 + tx+16j]
        float sv[4][4];
#pragma unroll
        for (int i = 0; i < 4; i++)
#pragma unroll
            for (int j = 0; j < 4; j++) sv[i][j] = 0.0f;

#pragma unroll
        for (int d = 0; d < 64; d++) {
            float a[4], q[4];
#pragma unroll
            for (int i = 0; i < 4; i++) a[i] = Ks[(4 * ty + i) * LDS + d];
#pragma unroll
            for (int j = 0; j < 4; j++) q[j] = Qs[(tx + 16 * j) * LDS + d];
#pragma unroll
            for (int i = 0; i < 4; i++)
#pragma unroll
                for (int j = 0; j < 4; j++) sv[i][j] += a[i] * q[j];
        }

        // scale + column mask
#pragma unroll
        for (int j = 0; j < 4; j++) {
            bool masked = (ms[tx + 16 * j] == 0);
#pragma unroll
            for (int i = 0; i < 4; i++)
                sv[i][j] = masked ? NEG_INF_F : sv[i][j] * scale;
        }

        // Online softmax per row (16-lane reductions; lanes with same ty are
        // 16 contiguous lanes of the warp, so xor-shfl 1..8 stays in-group).
#pragma unroll
        for (int i = 0; i < 4; i++) {
            float rm = fmaxf(fmaxf(sv[i][0], sv[i][1]),
                             fmaxf(sv[i][2], sv[i][3]));
#pragma unroll
            for (int off = 1; off < 16; off <<= 1)
                rm = fmaxf(rm, __shfl_xor_sync(0xffffffffu, rm, off));
            float mn = fmaxf(m_i[i], rm);
            float alpha = __expf(m_i[i] - mn);
            m_i[i] = mn;
            float rs = 0.0f;
#pragma unroll
            for (int j = 0; j < 4; j++) {
                float p = __expf(sv[i][j] - mn);
                sv[i][j] = p;
                rs += p;
            }
#pragma unroll
            for (int off = 1; off < 16; off <<= 1)
                rs += __shfl_xor_sync(0xffffffffu, rs, off);
            l_i[i] = l_i[i] * alpha + rs;
#pragma unroll
            for (int j = 0; j < 4; j++) O[i][j] *= alpha;
        }

        // Stage P into smem (consecutive tx -> conflict-free)
#pragma unroll
        for (int i = 0; i < 4; i++)
#pragma unroll
            for (int j = 0; j < 4; j++)
                Ps[(4 * ty + i) * LDS + tx + 16 * j] = sv[i][j];
        __syncthreads();

        // Phase 2: O[i][4tx+j] += sum_c Ps[4ty+i][c] * Vs[c][4tx+j]
#pragma unroll
        for (int c = 0; c < 64; c++) {
            float p[4];
#pragma unroll
            for (int i = 0; i < 4; i++) p[i] = Ps[(4 * ty + i) * LDS + c];
            float4 v = *(const float4*)&Vs[c * LDS + 4 * tx];
#pragma unroll
            for (int i = 0; i < 4; i++) {
                O[i][0] += p[i] * v.x;
                O[i][1] += p[i] * v.y;
                O[i][2] += p[i] * v.z;
                O[i][3] += p[i] * v.w;
            }
        }
    }

    // Epilogue: normalize and store
#pragma unroll
    for (int i = 0; i < 4; i++) {
        float inv = 1.0f / l_i[i];
        int r = r0 + 4 * ty + i;
        float4 o4 = make_float4(O[i][0] * inv, O[i][1] * inv,
                                O[i][2] * inv, O[i][3] * inv);
        *(float4*)&out[((size_t)b * SS + r) * DD + 4 * tx] = o4;
    }
}

extern "C" void kernel_launch(void* const* d_in, const int* in_sizes, int n_in,
                              void* d_out, int out_size) {
    const float* x    = (const float*)d_in[0];
    const int*   mask = (const int*)d_in[1];
    const float* Wk   = (const float*)d_in[2];
    const float* Wq   = (const float*)d_in[3];
    const float* Wv   = (const float*)d_in[4];
    float* out = (float*)d_out;

    // Projections: 16384 rows / 64 per block
    proj_kernel<<<256, 256>>>(x, Wk, Wq, Wv);

    // Attention: 64 row-blocks x 4 batches
    const int smem_bytes = 4 * 64 * LDS * (int)sizeof(float) + 64 * (int)sizeof(int);
    cudaFuncSetAttribute(attn_kernel,
                         cudaFuncAttributeMaxDynamicSharedMemorySize, smem_bytes);
    dim3 grid(64, 4);
    attn_kernel<<<grid, 256, smem_bytes>>>(mask, out);
}

// round 4
// speedup vs baseline: 1.5933x; 1.5933x over previous
#include <cuda_runtime.h>
#include <cuda_bf16.h>
#include <cstdint>

#define BB 4
#define SS 4096
#define HH 1024
#define DD 64

// Scratch for K, Q, V projections: 3 x [B*S, D] fp32 = 12 MB
__device__ float g_KQV[3][BB * SS * DD];

// ===========================================================================
// Projection kernel (unchanged from R2 — known good, ~196us)
// ===========================================================================
__global__ void proj_kernel(const float* __restrict__ x,
                            const float* __restrict__ Wk,
                            const float* __restrict__ Wq,
                            const float* __restrict__ Wv) {
    __shared__ float Xs[64][17];
    __shared__ float Ws[192][17];

    const int tid = threadIdx.x;
    const int ty = tid >> 4;
    const int tx = tid & 15;
    const int m0 = blockIdx.x * 64;

    float acc[4][12];
#pragma unroll
    for (int i = 0; i < 4; i++)
#pragma unroll
        for (int j = 0; j < 12; j++) acc[i][j] = 0.0f;

    for (int k0 = 0; k0 < HH; k0 += 16) {
#pragma unroll
        for (int i = 0; i < 4; i++) {
            int idx = tid + i * 256;
            int r = idx >> 4, c = idx & 15;
            Xs[r][c] = x[(size_t)(m0 + r) * HH + k0 + c];
        }
#pragma unroll
        for (int i = 0; i < 12; i++) {
            int idx = tid + i * 256;
            int r = idx >> 4, c = idx & 15;
            const float* W = (r < 64) ? Wk : ((r < 128) ? Wq : Wv);
            int rr = r & 63;
            Ws[r][c] = W[(size_t)rr * HH + k0 + c];
        }
        __syncthreads();

#pragma unroll
        for (int kk = 0; kk < 16; kk++) {
            float a[4], bb[12];
#pragma unroll
            for (int i = 0; i < 4; i++) a[i] = Xs[ty * 4 + i][kk];
#pragma unroll
            for (int j = 0; j < 12; j++) bb[j] = Ws[tx + 16 * j][kk];
#pragma unroll
            for (int i = 0; i < 4; i++)
#pragma unroll
                for (int j = 0; j < 12; j++) acc[i][j] += a[i] * bb[j];
        }
        __syncthreads();
    }

#pragma unroll
    for (int j = 0; j < 12; j++) {
        int n = tx + 16 * j;
        float* out = g_KQV[n >> 6];
        int d = n & 63;
#pragma unroll
        for (int i = 0; i < 4; i++)
            out[(size_t)(m0 + 4 * ty + i) * DD + d] = acc[i][j];
    }
}

// ===========================================================================
// mma.sync helpers (plain sm_103 — no tcgen05)
// ===========================================================================
__device__ __forceinline__ uint32_t smem_u32_of(const void* p) {
    uint32_t addr;
    asm("{ .reg .u64 tmp; cvta.to.shared.u64 tmp, %1; cvt.u32.u64 %0, tmp; }"
        : "=r"(addr) : "l"(p));
    return addr;
}

__device__ __forceinline__ void ldsm_x4(uint32_t* r, uint32_t addr) {
    asm volatile("ldmatrix.sync.aligned.m8n8.x4.shared.b16 {%0,%1,%2,%3}, [%4];"
                 : "=r"(r[0]), "=r"(r[1]), "=r"(r[2]), "=r"(r[3]) : "r"(addr));
}
__device__ __forceinline__ void ldsm_x2(uint32_t* r, uint32_t addr) {
    asm volatile("ldmatrix.sync.aligned.m8n8.x2.shared.b16 {%0,%1}, [%2];"
                 : "=r"(r[0]), "=r"(r[1]) : "r"(addr));
}
__device__ __forceinline__ void mma16816(float* d, const uint32_t* a,
                                         const uint32_t* b) {
    asm volatile(
        "mma.sync.aligned.m16n8k16.row.col.f32.bf16.bf16.f32 "
        "{%0,%1,%2,%3}, {%4,%5,%6,%7}, {%8,%9}, {%0,%1,%2,%3};"
        : "+f"(d[0]), "+f"(d[1]), "+f"(d[2]), "+f"(d[3])
        : "r"(a[0]), "r"(a[1]), "r"(a[2]), "r"(a[3]), "r"(b[0]), "r"(b[1]));
}

__device__ __forceinline__ uint32_t pack_bf16x2(float lo, float hi) {
    __nv_bfloat162 t = __floats2bfloat162_rn(lo, hi);
    return *(uint32_t*)&t;
}
__device__ __forceinline__ void bsplit(float v, float& h, float& l) {
    __nv_bfloat16 hb = __float2bfloat16(v);
    h = __bfloat162float(hb);
    l = v - h;
}

// Padded-row layout: LD = 72 bf16 per row (144 B = 36 words) -> ldmatrix
// fragment addresses hit banks (4*dr + c) : conflict-free.
#define LDP 72

// A-fragment ldmatrix.x4 address: 16x16 tile at (row0, col0)
__device__ __forceinline__ uint32_t a_addr(uint32_t base, int row0, int col0,
                                           int lane) {
    int t = lane >> 3, ri = lane & 7;
    int row = row0 + ri + ((t & 1) << 3);
    int col = col0 + ((t >> 1) << 3);
    return base + (uint32_t)(row * LDP + col) * 2;
}
// B-fragment ldmatrix.x2 address: memory rows = n (8 of them), k contiguous
__device__ __forceinline__ uint32_t b_addr(uint32_t base, int n0, int k0,
                                           int lane) {
    int l = lane & 15;
    int row = n0 + (l & 7);
    int col = k0 + ((l >> 3) << 3);
    return base + (uint32_t)(row * LDP + col) * 2;
}

// SMEM layout (byte offsets into dynamic smem)
#define KHI_OFF 0
#define KLO_OFF (KHI_OFF + 128 * LDP * 2)      // 18432 each
#define QHI_OFF (KLO_OFF + 128 * LDP * 2)
#define QLO_OFF (QHI_OFF + 64 * LDP * 2)       // 9216 each
#define VHI_OFF (QLO_OFF + 64 * LDP * 2)
#define VLO_OFF (VHI_OFF + 64 * LDP * 2)
#define PHI_OFF (VLO_OFF + 64 * LDP * 2)
#define PLO_OFF (PHI_OFF + 128 * LDP * 2)
#define MS_OFF  (PLO_OFF + 128 * LDP * 2)      // 64 ints
#define LSH_OFF (MS_OFF + 256)                 // 2*128 floats
#define SMEM_TOTAL (LSH_OFF + 1024)

// ===========================================================================
// Attention via mma.sync bf16 with hi/lo split (3 passes per GEMM):
//   out[b,r,:] = softmax_t( K_r . Q_t / 8 , col-mask on t ) @ V
// CTA: 128 K-rows, 8 warps in 4(M)x2(N) grid, warp tile 32x32.
// 64 steps over t-blocks of 64. S fresh per step; O accumulates in regs.
// ===========================================================================
__global__ void __launch_bounds__(256) attn_mma_kernel(const int* __restrict__ mask,
                                                       float* __restrict__ out) {
    extern __shared__ char smem[];
    const uint32_t sb = smem_u32_of(smem);

    const int tid = threadIdx.x;
    const int wid = tid >> 5;
    const int lane = tid & 31;
    const int warp_m = wid & 3;
    const int warp_n = wid >> 2;
    const int b = blockIdx.y;
    const int r0 = blockIdx.x * 128;

    const float* K = g_KQV[0] + (size_t)b * SS * DD;
    const float* Q = g_KQV[1] + (size_t)b * SS * DD;
    const float* V = g_KQV[2] + (size_t)b * SS * DD;

    int* msp = (int*)(smem + MS_OFF);

    // ---- K tile: load once, split hi/lo ----
#pragma unroll
    for (int j = 0; j < 8; j++) {
        int idx = tid + 256 * j;
        int row = idx >> 4, c4 = idx & 15;
        float4 v = *(const float4*)&K[(size_t)(r0 + row) * DD + c4 * 4];
        float h0, l0, h1, l1, h2, l2, h3, l3;
        bsplit(v.x, h0, l0); bsplit(v.y, h1, l1);
        bsplit(v.z, h2, l2); bsplit(v.w, h3, l3);
        uint2 hp = make_uint2(pack_bf16x2(h0, h1), pack_bf16x2(h2, h3));
        uint2 lp = make_uint2(pack_bf16x2(l0, l1), pack_bf16x2(l2, l3));
        *(uint2*)(smem + KHI_OFF + row * LDP * 2 + c4 * 8) = hp;
        *(uint2*)(smem + KLO_OFF + row * LDP * 2 + c4 * 8) = lp;
    }

    // ---- prefetch step 0 ----
    const int qrow = tid >> 4, qc4 = tid & 15;   // idx base pattern
    const int vd = tid & 63, vpb = tid >> 6;     // d, pair-base
    float4 q4[4];
    float vv[16];
    int mk = 0;
#pragma unroll
    for (int j = 0; j < 4; j++) {
        int idx = tid + 256 * j;
        q4[j] = *(const float4*)&Q[(size_t)(idx >> 4) * DD + (idx & 15) * 4];
    }
#pragma unroll
    for (int j = 0; j < 8; j++) {
        int p = vpb + 4 * j;
        vv[2 * j + 0] = V[(size_t)(2 * p + 0) * DD + vd];
        vv[2 * j + 1] = V[(size_t)(2 * p + 1) * DD + vd];
    }
    if (tid < 64) mk = mask[b * SS + tid];

    float oacc[2][4][4];
#pragma unroll
    for (int mt = 0; mt < 2; mt++)
#pragma unroll
        for (int nt = 0; nt < 4; nt++)
#pragma unroll
            for (int e = 0; e < 4; e++) oacc[mt][nt][e] = 0.0f;
    float l_part[4] = {0.0f, 0.0f, 0.0f, 0.0f};

#pragma unroll 1
    for (int step = 0; step < 64; step++) {
        // ---- [A] STS Q/V/mask tiles ----
#pragma unroll
        for (int j = 0; j < 4; j++) {
            int idx = tid + 256 * j;
            int row = idx >> 4, c4 = idx & 15;
            float4 v = q4[j];
            float h0, l0, h1, l1, h2, l2, h3, l3;
            bsplit(v.x, h0, l0); bsplit(v.y, h1, l1);
            bsplit(v.z, h2, l2); bsplit(v.w, h3, l3);
            uint2 hp = make_uint2(pack_bf16x2(h0, h1), pack_bf16x2(h2, h3));
            uint2 lp = make_uint2(pack_bf16x2(l0, l1), pack_bf16x2(l2, l3));
            *(uint2*)(smem + QHI_OFF + row * LDP * 2 + c4 * 8) = hp;
            *(uint2*)(smem + QLO_OFF + row * LDP * 2 + c4 * 8) = lp;
        }
#pragma unroll
        for (int j = 0; j < 8; j++) {
            int p = vpb + 4 * j;
            float h0, l0, h1, l1;
            bsplit(vv[2 * j + 0], h0, l0);
            bsplit(vv[2 * j + 1], h1, l1);
            *(uint32_t*)(smem + VHI_OFF + vd * LDP * 2 + p * 4) = pack_bf16x2(h0, h1);
            *(uint32_t*)(smem + VLO_OFF + vd * LDP * 2 + p * 4) = pack_bf16x2(l0, l1);
        }
        if (tid < 64) msp[tid] = mk;
        __syncthreads();

        // ---- prefetch next step (overlaps MMA work) ----
        if (step + 1 < 64) {
            int t0n = (step + 1) * 64;
#pragma unroll
            for (int j = 0; j < 4; j++) {
                int idx = tid + 256 * j;
                q4[j] = *(const float4*)&Q[(size_t)(t0n + (idx >> 4)) * DD + (idx & 15) * 4];
            }
#pragma unroll
            for (int j = 0; j < 8; j++) {
                int p = vpb + 4 * j;
                vv[2 * j + 0] = V[(size_t)(t0n + 2 * p + 0) * DD + vd];
                vv[2 * j + 1] = V[(size_t)(t0n + 2 * p + 1) * DD + vd];
            }
            if (tid < 64) mk = mask[b * SS + t0n + tid];
        }

        // ---- [B] MMA1: S = K . Q^T  (3 bf16-split passes) ----
        float sacc[2][4][4];
#pragma unroll
        for (int mt = 0; mt < 2; mt++)
#pragma unroll
            for (int nt = 0; nt < 4; nt++)
#pragma unroll
                for (int e = 0; e < 4; e++) sacc[mt][nt][e] = 0.0f;

#pragma unroll
        for (int pass = 0; pass < 3; pass++) {
            uint32_t Ab = sb + ((pass == 2) ? KLO_OFF : KHI_OFF);
            uint32_t Bb = sb + ((pass == 1) ? QLO_OFF : QHI_OFF);
#pragma unroll
            for (int kc = 0; kc < 4; kc++) {
                uint32_t af[2][4], bf[4][2];
#pragma unroll
                for (int mt = 0; mt < 2; mt++)
                    ldsm_x4(af[mt], a_addr(Ab, warp_m * 32 + mt * 16, kc * 16, lane));
#pragma unroll
                for (int nt = 0; nt < 4; nt++)
                    ldsm_x2(bf[nt], b_addr(Bb, warp_n * 32 + nt * 8, kc * 16, lane));
#pragma unroll
                for (int mt = 0; mt < 2; mt++)
#pragma unroll
                    for (int nt = 0; nt < 4; nt++)
                        mma16816(sacc[mt][nt], af[mt], bf[nt]);
            }
        }

        // ---- softmax (no max subtraction; scores bounded) ----
        int mcol[8];
#pragma unroll
        for (int nt = 0; nt < 4; nt++)
#pragma unroll
            for (int e = 0; e < 2; e++)
                mcol[nt * 2 + e] = msp[warp_n * 32 + nt * 8 + (lane & 3) * 2 + e];

#pragma unroll
        for (int mt = 0; mt < 2; mt++)
#pragma unroll
            for (int rp = 0; rp < 2; rp++) {
                float lp = 0.0f;
#pragma unroll
                for (int nt = 0; nt < 4; nt++)
#pragma unroll
                    for (int e = 0; e < 2; e++) {
                        float s = sacc[mt][nt][rp * 2 + e];
                        float pv = mcol[nt * 2 + e] ? __expf(s * 0.125f) : 0.0f;
                        sacc[mt][nt][rp * 2 + e] = pv;
                        lp += pv;
                    }
                l_part[mt * 2 + rp] += lp;
            }

        // ---- [C] STS P hi/lo ----
#pragma unroll
        for (int mt = 0; mt < 2; mt++)
#pragma unroll
            for (int rp = 0; rp < 2; rp++) {
                int row = warp_m * 32 + mt * 16 + rp * 8 + (lane >> 2);
#pragma unroll
                for (int nt = 0; nt < 4; nt++) {
                    int col = warp_n * 32 + nt * 8 + (lane & 3) * 2;
                    float h0, l0, h1, l1;
                    bsplit(sacc[mt][nt][rp * 2 + 0], h0, l0);
                    bsplit(sacc[mt][nt][rp * 2 + 1], h1, l1);
                    *(uint32_t*)(smem + PHI_OFF + row * LDP * 2 + col * 2) =
                        pack_bf16x2(h0, h1);
                    *(uint32_t*)(smem + PLO_OFF + row * LDP * 2 + col * 2) =
                        pack_bf16x2(l0, l1);
                }
            }
        __syncthreads();

        // ---- [D] MMA2: O += P . V  (3 bf16-split passes) ----
#pragma unroll
        for (int pass = 0; pass < 3; pass++) {
            uint32_t Ab = sb + ((pass == 2) ? PLO_OFF : PHI_OFF);
            uint32_t Bb = sb + ((pass == 1) ? VLO_OFF : VHI_OFF);
#pragma unroll
            for (int kc = 0; kc < 4; kc++) {
                uint32_t af[2][4], bf[4][2];
#pragma unroll
                for (int mt = 0; mt < 2; mt++)
                    ldsm_x4(af[mt], a_addr(Ab, warp_m * 32 + mt * 16, kc * 16, lane));
#pragma unroll
                for (int nt = 0; nt < 4; nt++)
                    ldsm_x2(bf[nt], b_addr(Bb, warp_n * 32 + nt * 8, kc * 16, lane));
#pragma unroll
                for (int mt = 0; mt < 2; mt++)
#pragma unroll
                    for (int nt = 0; nt < 4; nt++)
                        mma16816(oacc[mt][nt], af[mt], bf[nt]);
            }
        }
        __syncthreads();
    }

    // ---- epilogue: reduce l, normalize, store ----
    float* l_sh = (float*)(smem + LSH_OFF);
#pragma unroll
    for (int i = 0; i < 4; i++) {
        float l = l_part[i];
        l += __shfl_xor_sync(0xffffffffu, l, 1);
        l += __shfl_xor_sync(0xffffffffu, l, 2);
        l_part[i] = l;
    }
    if ((lane & 3) == 0) {
#pragma unroll
        for (int mt = 0; mt < 2; mt++)
#pragma unroll
            for (int rp = 0; rp < 2; rp++) {
                int row = warp_m * 32 + mt * 16 + rp * 8 + (lane >> 2);
                l_sh[warp_n * 128 + row] = l_part[mt * 2 + rp];
            }
    }
    __syncthreads();

#pragma unroll
    for (int mt = 0; mt < 2; mt++)
#pragma unroll
        for (int rp = 0; rp < 2; rp++) {
            int row = warp_m * 32 + mt * 16 + rp * 8 + (lane >> 2);
            float inv = 1.0f / (l_sh[row] + l_sh[128 + row]);
#pragma unroll
            for (int nt = 0; nt < 4; nt++) {
                int d0 = warp_n * 32 + nt * 8 + (lane & 3) * 2;
                float2 o2 = make_float2(oacc[mt][nt][rp * 2 + 0] * inv,
                                        oacc[mt][nt][rp * 2 + 1] * inv);
                *(float2*)&out[((size_t)b * SS + r0 + row) * DD + d0] = o2;
            }
        }
}

extern "C" void kernel_launch(void* const* d_in, const int* in_sizes, int n_in,
                              void* d_out, int out_size) {
    const float* x    = (const float*)d_in[0];
    const int*   mask = (const int*)d_in[1];
    const float* Wk   = (const float*)d_in[2];
    const float* Wq   = (const float*)d_in[3];
    const float* Wv   = (const float*)d_in[4];
    float* out = (float*)d_out;

    proj_kernel<<<256, 256>>>(x, Wk, Wq, Wv);

    cudaFuncSetAttribute(attn_mma_kernel,
                         cudaFuncAttributeMaxDynamicSharedMemorySize, SMEM_TOTAL);
    dim3 grid(32, 4);
    attn_mma_kernel<<<grid, 256, SMEM_TOTAL>>>(mask, out);
}

// round 5
// speedup vs baseline: 2.3837x; 1.4961x over previous
#include <cuda_runtime.h>
#include <cuda_bf16.h>
#include <cstdint>

#define BB 4
#define SS 4096
#define HH 1024
#define DD 64

// Scratch for K, Q, V projections: 3 x [B*S, D] fp32 = 12 MB
__device__ float g_KQV[3][BB * SS * DD];

// ===========================================================================
// Common mma.sync helpers (plain sm_103 — no tcgen05)
// ===========================================================================
__device__ __forceinline__ uint32_t smem_u32_of(const void* p) {
    uint32_t addr;
    asm("{ .reg .u64 tmp; cvta.to.shared.u64 tmp, %1; cvt.u32.u64 %0, tmp; }"
        : "=r"(addr) : "l"(p));
    return addr;
}

__device__ __forceinline__ void ldsm_x4(uint32_t* r, uint32_t addr) {
    asm volatile("ldmatrix.sync.aligned.m8n8.x4.shared.b16 {%0,%1,%2,%3}, [%4];"
                 : "=r"(r[0]), "=r"(r[1]), "=r"(r[2]), "=r"(r[3]) : "r"(addr));
}
__device__ __forceinline__ void ldsm_x2(uint32_t* r, uint32_t addr) {
    asm volatile("ldmatrix.sync.aligned.m8n8.x2.shared.b16 {%0,%1}, [%2];"
                 : "=r"(r[0]), "=r"(r[1]) : "r"(addr));
}
__device__ __forceinline__ void mma16816(float* d, const uint32_t* a,
                                         const uint32_t* b) {
    asm volatile(
        "mma.sync.aligned.m16n8k16.row.col.f32.bf16.bf16.f32 "
        "{%0,%1,%2,%3}, {%4,%5,%6,%7}, {%8,%9}, {%0,%1,%2,%3};"
        : "+f"(d[0]), "+f"(d[1]), "+f"(d[2]), "+f"(d[3])
        : "r"(a[0]), "r"(a[1]), "r"(a[2]), "r"(a[3]), "r"(b[0]), "r"(b[1]));
}

__device__ __forceinline__ uint32_t pack_bf16x2(float lo, float hi) {
    __nv_bfloat162 t = __floats2bfloat162_rn(lo, hi);
    return *(uint32_t*)&t;
}
__device__ __forceinline__ void bsplit(float v, float& h, float& l) {
    __nv_bfloat16 hb = __float2bfloat16(v);
    h = __bfloat162float(hb);
    l = v - h;
}

// A-fragment ldmatrix.x4 address (16x16 tile at row0,col0), row stride ld bf16
__device__ __forceinline__ uint32_t a_addr_ld(uint32_t base, int row0, int col0,
                                              int lane, int ld) {
    int t = lane >> 3, ri = lane & 7;
    int row = row0 + ri + ((t & 1) << 3);
    int col = col0 + ((t >> 1) << 3);
    return base + (uint32_t)(row * ld + col) * 2;
}
// B-fragment ldmatrix.x2 (one n8k16 tile)
__device__ __forceinline__ uint32_t b_addr_ld(uint32_t base, int n0, int k0,
                                              int lane, int ld) {
    int l = lane & 15;
    int row = n0 + (l & 7);
    int col = k0 + ((l >> 3) << 3);
    return base + (uint32_t)(row * ld + col) * 2;
}
// B-pair ldmatrix.x4 (two adjacent n8k16 tiles: regs {r0,r1}=tile0, {r2,r3}=tile1)
__device__ __forceinline__ uint32_t b2_addr_ld(uint32_t base, int n0, int k0,
                                               int lane, int ld) {
    int row = n0 + ((lane >> 4) << 3) + (lane & 7);
    int col = k0 + (((lane >> 3) & 1) << 3);
    return base + (uint32_t)(row * ld + col) * 2;
}

// ===========================================================================
// Projection via mma.sync bf16 3-pass split:
//   [K;Q;V][m, n] = x[m, :] . W[n, :],  W = [Wk; Wq; Wv] (192 rows)
// CTA: BM=128, BN=192, BK=32. 8 warps 4(M)x2(N), warp tile 32x96. Grid 128.
// ===========================================================================
#define PLDP 40                         // bf16 per smem row (32 data + 8 pad)
#define PX_HI 0
#define PX_LO (PX_HI + 128 * PLDP * 2)  // 10240 each
#define PW_HI (PX_LO + 128 * PLDP * 2)
#define PW_LO (PW_HI + 192 * PLDP * 2)  // 15360 each
#define PSMEM (PW_LO + 192 * PLDP * 2)  // 51200 bytes

__global__ void __launch_bounds__(256) proj_mma_kernel(const float* __restrict__ x,
                                                       const float* __restrict__ Wk,
                                                       const float* __restrict__ Wq,
                                                       const float* __restrict__ Wv) {
    extern __shared__ char smem[];
    const uint32_t sb = smem_u32_of(smem);

    const int tid = threadIdx.x;
    const int wid = tid >> 5;
    const int lane = tid & 31;
    const int warp_m = wid & 3;
    const int warp_n = wid >> 2;
    const int m0 = blockIdx.x * 128;

    float4 xr[4], wr[6];

    // prefetch iter 0
#pragma unroll
    for (int j = 0; j < 4; j++) {
        int idx = tid + 256 * j;
        xr[j] = *(const float4*)&x[(size_t)(m0 + (idx >> 3)) * HH + (idx & 7) * 4];
    }
#pragma unroll
    for (int j = 0; j < 6; j++) {
        int idx = tid + 256 * j;
        int row = idx >> 3;
        const float* W = (row < 64) ? Wk : ((row < 128) ? Wq : Wv);
        wr[j] = *(const float4*)&W[(size_t)(row & 63) * HH + (idx & 7) * 4];
    }

    float acc[2][12][4];
#pragma unroll
    for (int mt = 0; mt < 2; mt++)
#pragma unroll
        for (int nn = 0; nn < 12; nn++)
#pragma unroll
            for (int e = 0; e < 4; e++) acc[mt][nn][e] = 0.0f;

#pragma unroll 1
    for (int it = 0; it < 32; it++) {
        // ---- STS (split hi/lo) ----
#pragma unroll
        for (int j = 0; j < 4; j++) {
            int idx = tid + 256 * j;
            int row = idx >> 3, c4 = idx & 7;
            float h0, l0, h1, l1, h2, l2, h3, l3;
            bsplit(xr[j].x, h0, l0); bsplit(xr[j].y, h1, l1);
            bsplit(xr[j].z, h2, l2); bsplit(xr[j].w, h3, l3);
            *(uint2*)(smem + PX_HI + row * PLDP * 2 + c4 * 8) =
                make_uint2(pack_bf16x2(h0, h1), pack_bf16x2(h2, h3));
            *(uint2*)(smem + PX_LO + row * PLDP * 2 + c4 * 8) =
                make_uint2(pack_bf16x2(l0, l1), pack_bf16x2(l2, l3));
        }
#pragma unroll
        for (int j = 0; j < 6; j++) {
            int idx = tid + 256 * j;
            int row = idx >> 3, c4 = idx & 7;
            float h0, l0, h1, l1, h2, l2, h3, l3;
            bsplit(wr[j].x, h0, l0); bsplit(wr[j].y, h1, l1);
            bsplit(wr[j].z, h2, l2); bsplit(wr[j].w, h3, l3);
            *(uint2*)(smem + PW_HI + row * PLDP * 2 + c4 * 8) =
                make_uint2(pack_bf16x2(h0, h1), pack_bf16x2(h2, h3));
            *(uint2*)(smem + PW_LO + row * PLDP * 2 + c4 * 8) =
                make_uint2(pack_bf16x2(l0, l1), pack_bf16x2(l2, l3));
        }
        __syncthreads();

        // ---- prefetch next slab (overlaps MMA) ----
        if (it + 1 < 32) {
            int k0 = (it + 1) * 32;
#pragma unroll
            for (int j = 0; j < 4; j++) {
                int idx = tid + 256 * j;
                xr[j] = *(const float4*)&x[(size_t)(m0 + (idx >> 3)) * HH + k0 + (idx & 7) * 4];
            }
#pragma unroll
            for (int j = 0; j < 6; j++) {
                int idx = tid + 256 * j;
                int row = idx >> 3;
                const float* W = (row < 64) ? Wk : ((row < 128) ? Wq : Wv);
                wr[j] = *(const float4*)&W[(size_t)(row & 63) * HH + k0 + (idx & 7) * 4];
            }
        }

        // ---- MMA: 3-pass split, BK=32 (2 k-chunks) ----
#pragma unroll
        for (int kc = 0; kc < 2; kc++) {
            uint32_t ah[2][4], al[2][4];
#pragma unroll
            for (int mt = 0; mt < 2; mt++) {
                ldsm_x4(ah[mt], a_addr_ld(sb + PX_HI, warp_m * 32 + mt * 16, kc * 16, lane, PLDP));
                ldsm_x4(al[mt], a_addr_ld(sb + PX_LO, warp_m * 32 + mt * 16, kc * 16, lane, PLDP));
            }
#pragma unroll
            for (int nh = 0; nh < 2; nh++) {
                uint32_t bh[6][2], bl[6][2];
#pragma unroll
                for (int pp = 0; pp < 3; pp++) {
                    uint32_t tmp[4];
                    int n0 = warp_n * 96 + nh * 48 + pp * 16;
                    ldsm_x4(tmp, b2_addr_ld(sb + PW_HI, n0, kc * 16, lane, PLDP));
                    bh[2 * pp][0] = tmp[0]; bh[2 * pp][1] = tmp[1];
                    bh[2 * pp + 1][0] = tmp[2]; bh[2 * pp + 1][1] = tmp[3];
                    ldsm_x4(tmp, b2_addr_ld(sb + PW_LO, n0, kc * 16, lane, PLDP));
                    bl[2 * pp][0] = tmp[0]; bl[2 * pp][1] = tmp[1];
                    bl[2 * pp + 1][0] = tmp[2]; bl[2 * pp + 1][1] = tmp[3];
                }
#pragma unroll
                for (int mt = 0; mt < 2; mt++)
#pragma unroll
                    for (int nt = 0; nt < 6; nt++) {
                        float* d = acc[mt][nh * 6 + nt];
                        mma16816(d, ah[mt], bh[nt]);   // hi*hi
                        mma16816(d, ah[mt], bl[nt]);   // hi*lo
                        mma16816(d, al[mt], bh[nt]);   // lo*hi
                    }
            }
        }
        __syncthreads();
    }

    // ---- epilogue: scatter to g_KQV ----
#pragma unroll
    for (int mt = 0; mt < 2; mt++)
#pragma unroll
        for (int rp = 0; rp < 2; rp++) {
            int row = m0 + warp_m * 32 + mt * 16 + rp * 8 + (lane >> 2);
#pragma unroll
            for (int nn = 0; nn < 12; nn++) {
                int n = warp_n * 96 + nn * 8 + (lane & 3) * 2;
                float* dst = g_KQV[n >> 6];
                int d = n & 63;
                float2 o2 = make_float2(acc[mt][nn][rp * 2 + 0],
                                        acc[mt][nn][rp * 2 + 1]);
                *(float2*)&dst[(size_t)row * DD + d] = o2;
            }
        }
}

// ===========================================================================
// Attention via mma.sync bf16 with hi/lo split (unchanged from R4 — 245us)
// ===========================================================================
#define LDP 72

#define KHI_OFF 0
#define KLO_OFF (KHI_OFF + 128 * LDP * 2)
#define QHI_OFF (KLO_OFF + 128 * LDP * 2)
#define QLO_OFF (QHI_OFF + 64 * LDP * 2)
#define VHI_OFF (QLO_OFF + 64 * LDP * 2)
#define VLO_OFF (VHI_OFF + 64 * LDP * 2)
#define PHI_OFF (VLO_OFF + 64 * LDP * 2)
#define PLO_OFF (PHI_OFF + 128 * LDP * 2)
#define MS_OFF  (PLO_OFF + 128 * LDP * 2)
#define LSH_OFF (MS_OFF + 256)
#define SMEM_TOTAL (LSH_OFF + 1024)

__global__ void __launch_bounds__(256) attn_mma_kernel(const int* __restrict__ mask,
                                                       float* __restrict__ out) {
    extern __shared__ char smem[];
    const uint32_t sb = smem_u32_of(smem);

    const int tid = threadIdx.x;
    const int wid = tid >> 5;
    const int lane = tid & 31;
    const int warp_m = wid & 3;
    const int warp_n = wid >> 2;
    const int b = blockIdx.y;
    const int r0 = blockIdx.x * 128;

    const float* K = g_KQV[0] + (size_t)b * SS * DD;
    const float* Q = g_KQV[1] + (size_t)b * SS * DD;
    const float* V = g_KQV[2] + (size_t)b * SS * DD;

    int* msp = (int*)(smem + MS_OFF);

#pragma unroll
    for (int j = 0; j < 8; j++) {
        int idx = tid + 256 * j;
        int row = idx >> 4, c4 = idx & 15;
        float4 v = *(const float4*)&K[(size_t)(r0 + row) * DD + c4 * 4];
        float h0, l0, h1, l1, h2, l2, h3, l3;
        bsplit(v.x, h0, l0); bsplit(v.y, h1, l1);
        bsplit(v.z, h2, l2); bsplit(v.w, h3, l3);
        *(uint2*)(smem + KHI_OFF + row * LDP * 2 + c4 * 8) =
            make_uint2(pack_bf16x2(h0, h1), pack_bf16x2(h2, h3));
        *(uint2*)(smem + KLO_OFF + row * LDP * 2 + c4 * 8) =
            make_uint2(pack_bf16x2(l0, l1), pack_bf16x2(l2, l3));
    }

    const int vd = tid & 63, vpb = tid >> 6;
    float4 q4[4];
    float vv[16];
    int mk = 0;
#pragma unroll
    for (int j = 0; j < 4; j++) {
        int idx = tid + 256 * j;
        q4[j] = *(const float4*)&Q[(size_t)(idx >> 4) * DD + (idx & 15) * 4];
    }
#pragma unroll
    for (int j = 0; j < 8; j++) {
        int p = vpb + 4 * j;
        vv[2 * j + 0] = V[(size_t)(2 * p + 0) * DD + vd];
        vv[2 * j + 1] = V[(size_t)(2 * p + 1) * DD + vd];
    }
    if (tid < 64) mk = mask[b * SS + tid];

    float oacc[2][4][4];
#pragma unroll
    for (int mt = 0; mt < 2; mt++)
#pragma unroll
        for (int nt = 0; nt < 4; nt++)
#pragma unroll
            for (int e = 0; e < 4; e++) oacc[mt][nt][e] = 0.0f;
    float l_part[4] = {0.0f, 0.0f, 0.0f, 0.0f};

#pragma unroll 1
    for (int step = 0; step < 64; step++) {
#pragma unroll
        for (int j = 0; j < 4; j++) {
            int idx = tid + 256 * j;
            int row = idx >> 4, c4 = idx & 15;
            float4 v = q4[j];
            float h0, l0, h1, l1, h2, l2, h3, l3;
            bsplit(v.x, h0, l0); bsplit(v.y, h1, l1);
            bsplit(v.z, h2, l2); bsplit(v.w, h3, l3);
            *(uint2*)(smem + QHI_OFF + row * LDP * 2 + c4 * 8) =
                make_uint2(pack_bf16x2(h0, h1), pack_bf16x2(h2, h3));
            *(uint2*)(smem + QLO_OFF + row * LDP * 2 + c4 * 8) =
                make_uint2(pack_bf16x2(l0, l1), pack_bf16x2(l2, l3));
        }
#pragma unroll
        for (int j = 0; j < 8; j++) {
            int p = vpb + 4 * j;
            float h0, l0, h1, l1;
            bsplit(vv[2 * j + 0], h0, l0);
            bsplit(vv[2 * j + 1], h1, l1);
            *(uint32_t*)(smem + VHI_OFF + vd * LDP * 2 + p * 4) = pack_bf16x2(h0, h1);
            *(uint32_t*)(smem + VLO_OFF + vd * LDP * 2 + p * 4) = pack_bf16x2(l0, l1);
        }
        if (tid < 64) msp[tid] = mk;
        __syncthreads();

        if (step + 1 < 64) {
            int t0n = (step + 1) * 64;
#pragma unroll
            for (int j = 0; j < 4; j++) {
                int idx = tid + 256 * j;
                q4[j] = *(const float4*)&Q[(size_t)(t0n + (idx >> 4)) * DD + (idx & 15) * 4];
            }
#pragma unroll
            for (int j = 0; j < 8; j++) {
                int p = vpb + 4 * j;
                vv[2 * j + 0] = V[(size_t)(t0n + 2 * p + 0) * DD + vd];
                vv[2 * j + 1] = V[(size_t)(t0n + 2 * p + 1) * DD + vd];
            }
            if (tid < 64) mk = mask[b * SS + t0n + tid];
        }

        float sacc[2][4][4];
#pragma unroll
        for (int mt = 0; mt < 2; mt++)
#pragma unroll
            for (int nt = 0; nt < 4; nt++)
#pragma unroll
                for (int e = 0; e < 4; e++) sacc[mt][nt][e] = 0.0f;

#pragma unroll
        for (int pass = 0; pass < 3; pass++) {
            uint32_t Ab = sb + ((pass == 2) ? KLO_OFF : KHI_OFF);
            uint32_t Bb = sb + ((pass == 1) ? QLO_OFF : QHI_OFF);
#pragma unroll
            for (int kc = 0; kc < 4; kc++) {
                uint32_t af[2][4], bf[4][2];
#pragma unroll
                for (int mt = 0; mt < 2; mt++)
                    ldsm_x4(af[mt], a_addr_ld(Ab, warp_m * 32 + mt * 16, kc * 16, lane, LDP));
#pragma unroll
                for (int nt = 0; nt < 4; nt++)
                    ldsm_x2(bf[nt], b_addr_ld(Bb, warp_n * 32 + nt * 8, kc * 16, lane, LDP));
#pragma unroll
                for (int mt = 0; mt < 2; mt++)
#pragma unroll
                    for (int nt = 0; nt < 4; nt++)
                        mma16816(sacc[mt][nt], af[mt], bf[nt]);
            }
        }

        int mcol[8];
#pragma unroll
        for (int nt = 0; nt < 4; nt++)
#pragma unroll
            for (int e = 0; e < 2; e++)
                mcol[nt * 2 + e] = msp[warp_n * 32 + nt * 8 + (lane & 3) * 2 + e];

#pragma unroll
        for (int mt = 0; mt < 2; mt++)
#pragma unroll
            for (int rp = 0; rp < 2; rp++) {
                float lp = 0.0f;
#pragma unroll
                for (int nt = 0; nt < 4; nt++)
#pragma unroll
                    for (int e = 0; e < 2; e++) {
                        float s = sacc[mt][nt][rp * 2 + e];
                        float pv = mcol[nt * 2 + e] ? __expf(s * 0.125f) : 0.0f;
                        sacc[mt][nt][rp * 2 + e] = pv;
                        lp += pv;
                    }
                l_part[mt * 2 + rp] += lp;
            }

#pragma unroll
        for (int mt = 0; mt < 2; mt++)
#pragma unroll
            for (int rp = 0; rp < 2; rp++) {
                int row = warp_m * 32 + mt * 16 + rp * 8 + (lane >> 2);
#pragma unroll
                for (int nt = 0; nt < 4; nt++) {
                    int col = warp_n * 32 + nt * 8 + (lane & 3) * 2;
                    float h0, l0, h1, l1;
                    bsplit(sacc[mt][nt][rp * 2 + 0], h0, l0);
                    bsplit(sacc[mt][nt][rp * 2 + 1], h1, l1);
                    *(uint32_t*)(smem + PHI_OFF + row * LDP * 2 + col * 2) =
                        pack_bf16x2(h0, h1);
                    *(uint32_t*)(smem + PLO_OFF + row * LDP * 2 + col * 2) =
                        pack_bf16x2(l0, l1);
                }
            }
        __syncthreads();

#pragma unroll
        for (int pass = 0; pass < 3; pass++) {
            uint32_t Ab = sb + ((pass == 2) ? PLO_OFF : PHI_OFF);
            uint32_t Bb = sb + ((pass == 1) ? VLO_OFF : VHI_OFF);
#pragma unroll
            for (int kc = 0; kc < 4; kc++) {
                uint32_t af[2][4], bf[4][2];
#pragma unroll
                for (int mt = 0; mt < 2; mt++)
                    ldsm_x4(af[mt], a_addr_ld(Ab, warp_m * 32 + mt * 16, kc * 16, lane, LDP));
#pragma unroll
                for (int nt = 0; nt < 4; nt++)
                    ldsm_x2(bf[nt], b_addr_ld(Bb, warp_n * 32 + nt * 8, kc * 16, lane, LDP));
#pragma unroll
                for (int mt = 0; mt < 2; mt++)
#pragma unroll
                    for (int nt = 0; nt < 4; nt++)
                        mma16816(oacc[mt][nt], af[mt], bf[nt]);
            }
        }
        __syncthreads();
    }

    float* l_sh = (float*)(smem + LSH_OFF);
#pragma unroll
    for (int i = 0; i < 4; i++) {
        float l = l_part[i];
        l += __shfl_xor_sync(0xffffffffu, l, 1);
        l += __shfl_xor_sync(0xffffffffu, l, 2);
        l_part[i] = l;
    }
    if ((lane & 3) == 0) {
#pragma unroll
        for (int mt = 0; mt < 2; mt++)
#pragma unroll
            for (int rp = 0; rp < 2; rp++) {
                int row = warp_m * 32 + mt * 16 + rp * 8 + (lane >> 2);
                l_sh[warp_n * 128 + row] = l_part[mt * 2 + rp];
            }
    }
    __syncthreads();

#pragma unroll
    for (int mt = 0; mt < 2; mt++)
#pragma unroll
        for (int rp = 0; rp < 2; rp++) {
            int row = warp_m * 32 + mt * 16 + rp * 8 + (lane >> 2);
            float inv = 1.0f / (l_sh[row] + l_sh[128 + row]);
#pragma unroll
            for (int nt = 0; nt < 4; nt++) {
                int d0 = warp_n * 32 + nt * 8 + (lane & 3) * 2;
                float2 o2 = make_float2(oacc[mt][nt][rp * 2 + 0] * inv,
                                        oacc[mt][nt][rp * 2 + 1] * inv);
                *(float2*)&out[((size_t)b * SS + r0 + row) * DD + d0] = o2;
            }
        }
}

extern "C" void kernel_launch(void* const* d_in, const int* in_sizes, int n_in,
                              void* d_out, int out_size) {
    const float* x    = (const float*)d_in[0];
    const int*   mask = (const int*)d_in[1];
    const float* Wk   = (const float*)d_in[2];
    const float* Wq   = (const float*)d_in[3];
    const float* Wv   = (const float*)d_in[4];
    float* out = (float*)d_out;

    cudaFuncSetAttribute(proj_mma_kernel,
                         cudaFuncAttributeMaxDynamicSharedMemorySize, PSMEM);
    proj_mma_kernel<<<128, 256, PSMEM>>>(x, Wk, Wq, Wv);

    cudaFuncSetAttribute(attn_mma_kernel,
                         cudaFuncAttributeMaxDynamicSharedMemorySize, SMEM_TOTAL);
    dim3 grid(32, 4);
    attn_mma_kernel<<<grid, 256, SMEM_TOTAL>>>(mask, out);
}

// round 6
// speedup vs baseline: 2.5850x; 1.0844x over previous
#include <cuda_runtime.h>
#include <cuda_bf16.h>
#include <cstdint>

#define BB 4
#define SS 4096
#define HH 1024
#define DD 64

// Scratch for K, Q, V projections: 3 x [B*S, D] fp32 = 12 MB
__device__ float g_KQV[3][BB * SS * DD];

// ===========================================================================
// Common mma.sync helpers (plain sm_103 — no tcgen05)
// ===========================================================================
__device__ __forceinline__ uint32_t smem_u32_of(const void* p) {
    uint32_t addr;
    asm("{ .reg .u64 tmp; cvta.to.shared.u64 tmp, %1; cvt.u32.u64 %0, tmp; }"
        : "=r"(addr) : "l"(p));
    return addr;
}

__device__ __forceinline__ void ldsm_x4(uint32_t* r, uint32_t addr) {
    asm volatile("ldmatrix.sync.aligned.m8n8.x4.shared.b16 {%0,%1,%2,%3}, [%4];"
                 : "=r"(r[0]), "=r"(r[1]), "=r"(r[2]), "=r"(r[3]) : "r"(addr));
}
__device__ __forceinline__ void mma16816(float* d, const uint32_t* a,
                                         const uint32_t* b) {
    asm volatile(
        "mma.sync.aligned.m16n8k16.row.col.f32.bf16.bf16.f32 "
        "{%0,%1,%2,%3}, {%4,%5,%6,%7}, {%8,%9}, {%0,%1,%2,%3};"
        : "+f"(d[0]), "+f"(d[1]), "+f"(d[2]), "+f"(d[3])
        : "r"(a[0]), "r"(a[1]), "r"(a[2]), "r"(a[3]), "r"(b[0]), "r"(b[1]));
}

__device__ __forceinline__ uint32_t pack_bf16x2(float lo, float hi) {
    __nv_bfloat162 t = __floats2bfloat162_rn(lo, hi);
    return *(uint32_t*)&t;
}
__device__ __forceinline__ void bsplit(float v, float& h, float& l) {
    __nv_bfloat16 hb = __float2bfloat16(v);
    h = __bfloat162float(hb);
    l = v - h;
}
__device__ __forceinline__ float bhi(float v) {
    return __bfloat162float(__float2bfloat16(v));
}

// A-fragment ldmatrix.x4 address (16x16 tile at row0,col0), row stride ld bf16
__device__ __forceinline__ uint32_t a_addr_ld(uint32_t base, int row0, int col0,
                                              int lane, int ld) {
    int t = lane >> 3, ri = lane & 7;
    int row = row0 + ri + ((t & 1) << 3);
    int col = col0 + ((t >> 1) << 3);
    return base + (uint32_t)(row * ld + col) * 2;
}
// B-pair ldmatrix.x4 (two adjacent n8k16 tiles: regs {r0,r1}=tile0, {r2,r3}=tile1)
__device__ __forceinline__ uint32_t b2_addr_ld(uint32_t base, int n0, int k0,
                                               int lane, int ld) {
    int row = n0 + ((lane >> 4) << 3) + (lane & 7);
    int col = k0 + (((lane >> 3) & 1) << 3);
    return base + (uint32_t)(row * ld + col) * 2;
}

// ===========================================================================
// Projection via mma.sync bf16 3-pass split (unchanged from R5 — ~60us)
// ===========================================================================
#define PLDP 40
#define PX_HI 0
#define PX_LO (PX_HI + 128 * PLDP * 2)
#define PW_HI (PX_LO + 128 * PLDP * 2)
#define PW_LO (PW_HI + 192 * PLDP * 2)
#define PSMEM (PW_LO + 192 * PLDP * 2)

__global__ void __launch_bounds__(256) proj_mma_kernel(const float* __restrict__ x,
                                                       const float* __restrict__ Wk,
                                                       const float* __restrict__ Wq,
                                                       const float* __restrict__ Wv) {
    extern __shared__ char smem[];
    const uint32_t sb = smem_u32_of(smem);

    const int tid = threadIdx.x;
    const int wid = tid >> 5;
    const int lane = tid & 31;
    const int warp_m = wid & 3;
    const int warp_n = wid >> 2;
    const int m0 = blockIdx.x * 128;

    float4 xr[4], wr[6];

#pragma unroll
    for (int j = 0; j < 4; j++) {
        int idx = tid + 256 * j;
        xr[j] = *(const float4*)&x[(size_t)(m0 + (idx >> 3)) * HH + (idx & 7) * 4];
    }
#pragma unroll
    for (int j = 0; j < 6; j++) {
        int idx = tid + 256 * j;
        int row = idx >> 3;
        const float* W = (row < 64) ? Wk : ((row < 128) ? Wq : Wv);
        wr[j] = *(const float4*)&W[(size_t)(row & 63) * HH + (idx & 7) * 4];
    }

    float acc[2][12][4];
#pragma unroll
    for (int mt = 0; mt < 2; mt++)
#pragma unroll
        for (int nn = 0; nn < 12; nn++)
#pragma unroll
            for (int e = 0; e < 4; e++) acc[mt][nn][e] = 0.0f;

#pragma unroll 1
    for (int it = 0; it < 32; it++) {
#pragma unroll
        for (int j = 0; j < 4; j++) {
            int idx = tid + 256 * j;
            int row = idx >> 3, c4 = idx & 7;
            float h0, l0, h1, l1, h2, l2, h3, l3;
            bsplit(xr[j].x, h0, l0); bsplit(xr[j].y, h1, l1);
            bsplit(xr[j].z, h2, l2); bsplit(xr[j].w, h3, l3);
            *(uint2*)(smem + PX_HI + row * PLDP * 2 + c4 * 8) =
                make_uint2(pack_bf16x2(h0, h1), pack_bf16x2(h2, h3));
            *(uint2*)(smem + PX_LO + row * PLDP * 2 + c4 * 8) =
                make_uint2(pack_bf16x2(l0, l1), pack_bf16x2(l2, l3));
        }
#pragma unroll
        for (int j = 0; j < 6; j++) {
            int idx = tid + 256 * j;
            int row = idx >> 3, c4 = idx & 7;
            float h0, l0, h1, l1, h2, l2, h3, l3;
            bsplit(wr[j].x, h0, l0); bsplit(wr[j].y, h1, l1);
            bsplit(wr[j].z, h2, l2); bsplit(wr[j].w, h3, l3);
            *(uint2*)(smem + PW_HI + row * PLDP * 2 + c4 * 8) =
                make_uint2(pack_bf16x2(h0, h1), pack_bf16x2(h2, h3));
            *(uint2*)(smem + PW_LO + row * PLDP * 2 + c4 * 8) =
                make_uint2(pack_bf16x2(l0, l1), pack_bf16x2(l2, l3));
        }
        __syncthreads();

        if (it + 1 < 32) {
            int k0 = (it + 1) * 32;
#pragma unroll
            for (int j = 0; j < 4; j++) {
                int idx = tid + 256 * j;
                xr[j] = *(const float4*)&x[(size_t)(m0 + (idx >> 3)) * HH + k0 + (idx & 7) * 4];
            }
#pragma unroll
            for (int j = 0; j < 6; j++) {
                int idx = tid + 256 * j;
                int row = idx >> 3;
                const float* W = (row < 64) ? Wk : ((row < 128) ? Wq : Wv);
                wr[j] = *(const float4*)&W[(size_t)(row & 63) * HH + k0 + (idx & 7) * 4];
            }
        }

#pragma unroll
        for (int kc = 0; kc < 2; kc++) {
            uint32_t ah[2][4], al[2][4];
#pragma unroll
            for (int mt = 0; mt < 2; mt++) {
                ldsm_x4(ah[mt], a_addr_ld(sb + PX_HI, warp_m * 32 + mt * 16, kc * 16, lane, PLDP));
                ldsm_x4(al[mt], a_addr_ld(sb + PX_LO, warp_m * 32 + mt * 16, kc * 16, lane, PLDP));
            }
#pragma unroll
            for (int nh = 0; nh < 2; nh++) {
                uint32_t bh[6][2], bl[6][2];
#pragma unroll
                for (int pp = 0; pp < 3; pp++) {
                    uint32_t tmp[4];
                    int n0 = warp_n * 96 + nh * 48 + pp * 16;
                    ldsm_x4(tmp, b2_addr_ld(sb + PW_HI, n0, kc * 16, lane, PLDP));
                    bh[2 * pp][0] = tmp[0]; bh[2 * pp][1] = tmp[1];
                    bh[2 * pp + 1][0] = tmp[2]; bh[2 * pp + 1][1] = tmp[3];
                    ldsm_x4(tmp, b2_addr_ld(sb + PW_LO, n0, kc * 16, lane, PLDP));
                    bl[2 * pp][0] = tmp[0]; bl[2 * pp][1] = tmp[1];
                    bl[2 * pp + 1][0] = tmp[2]; bl[2 * pp + 1][1] = tmp[3];
                }
#pragma unroll
                for (int mt = 0; mt < 2; mt++)
#pragma unroll
                    for (int nt = 0; nt < 6; nt++) {
                        float* d = acc[mt][nh * 6 + nt];
                        mma16816(d, ah[mt], bh[nt]);
                        mma16816(d, ah[mt], bl[nt]);
                        mma16816(d, al[mt], bh[nt]);
                    }
            }
        }
        __syncthreads();
    }

#pragma unroll
    for (int mt = 0; mt < 2; mt++)
#pragma unroll
        for (int rp = 0; rp < 2; rp++) {
            int row = m0 + warp_m * 32 + mt * 16 + rp * 8 + (lane >> 2);
#pragma unroll
            for (int nn = 0; nn < 12; nn++) {
                int n = warp_n * 96 + nn * 8 + (lane & 3) * 2;
                float* dst = g_KQV[n >> 6];
                int d = n & 63;
                float2 o2 = make_float2(acc[mt][nn][rp * 2 + 0],
                                        acc[mt][nn][rp * 2 + 1]);
                *(float2*)&dst[(size_t)row * DD + d] = o2;
            }
        }
}

// ===========================================================================
// Attention R6: warp owns 16 S-rows x full 64 t-cols.
//  - K A-fragments register-resident for the whole kernel
//  - P reused as MMA2 A-fragments directly from registers (no smem roundtrip)
//  - 2 syncthreads/step; warp-local l reduction
// ===========================================================================
#define LDP 72
#define AQH 0
#define AQL (AQH + 64 * LDP * 2)      // 9216 each
#define AVH (AQL + 64 * LDP * 2)
#define AVL (AVH + 64 * LDP * 2)
#define AMS (AVL + 64 * LDP * 2)      // 64 ints
#define ASMEM (AMS + 512)
// K staging (pre-loop only) overlays AQH.. : hi at 0, lo at 18432 (both 128*144)
#define KSH 0
#define KSL 18432

__global__ void __launch_bounds__(256) attn_mma_kernel(const int* __restrict__ mask,
                                                       float* __restrict__ out) {
    extern __shared__ char smem[];
    const uint32_t sb = smem_u32_of(smem);

    const int tid = threadIdx.x;
    const int wid = tid >> 5;          // 0..7 -> rows wid*16..+16
    const int lane = tid & 31;
    const int gid = lane >> 2;
    const int tig = lane & 3;
    const int b = blockIdx.y;
    const int r0 = blockIdx.x * 128;

    const float* K = g_KQV[0] + (size_t)b * SS * DD;
    const float* Q = g_KQV[1] + (size_t)b * SS * DD;
    const float* V = g_KQV[2] + (size_t)b * SS * DD;

    int* msp = (int*)(smem + AMS);

    // ---- stage K hi/lo in smem, pull A-fragments into registers ----
#pragma unroll
    for (int j = 0; j < 8; j++) {
        int idx = tid + 256 * j;
        int row = idx >> 4, c4 = idx & 15;
        float4 v = *(const float4*)&K[(size_t)(r0 + row) * DD + c4 * 4];
        float h0, l0, h1, l1, h2, l2, h3, l3;
        bsplit(v.x, h0, l0); bsplit(v.y, h1, l1);
        bsplit(v.z, h2, l2); bsplit(v.w, h3, l3);
        *(uint2*)(smem + KSH + row * LDP * 2 + c4 * 8) =
            make_uint2(pack_bf16x2(h0, h1), pack_bf16x2(h2, h3));
        *(uint2*)(smem + KSL + row * LDP * 2 + c4 * 8) =
            make_uint2(pack_bf16x2(l0, l1), pack_bf16x2(l2, l3));
    }
    __syncthreads();

    uint32_t Khf[4][4], Klf[4][4];
#pragma unroll
    for (int kc = 0; kc < 4; kc++) {
        ldsm_x4(Khf[kc], a_addr_ld(sb + KSH, wid * 16, kc * 16, lane, LDP));
        ldsm_x4(Klf[kc], a_addr_ld(sb + KSL, wid * 16, kc * 16, lane, LDP));
    }
    __syncthreads();   // staging area will be overwritten by Q/V tiles

    // ---- prefetch step 0 ----
    const int vd = tid & 63, vpb = tid >> 6;
    float4 q4[4];
    float vv[16];
    int mk = 0;
#pragma unroll
    for (int j = 0; j < 4; j++) {
        int idx = tid + 256 * j;
        q4[j] = *(const float4*)&Q[(size_t)(idx >> 4) * DD + (idx & 15) * 4];
    }
#pragma unroll
    for (int j = 0; j < 8; j++) {
        int p = vpb + 4 * j;
        vv[2 * j + 0] = V[(size_t)(2 * p + 0) * DD + vd];
        vv[2 * j + 1] = V[(size_t)(2 * p + 1) * DD + vd];
    }
    if (tid < 64) mk = mask[b * SS + tid];

    float oacc[8][4];
#pragma unroll
    for (int nt = 0; nt < 8; nt++)
#pragma unroll
        for (int e = 0; e < 4; e++) oacc[nt][e] = 0.0f;
    float l0 = 0.0f, l1 = 0.0f;

#pragma unroll 1
    for (int step = 0; step < 64; step++) {
        // ---- STS Q/V/mask ----
#pragma unroll
        for (int j = 0; j < 4; j++) {
            int idx = tid + 256 * j;
            int row = idx >> 4, c4 = idx & 15;
            float h0, lo0, h1, lo1, h2, lo2, h3, lo3;
            bsplit(q4[j].x, h0, lo0); bsplit(q4[j].y, h1, lo1);
            bsplit(q4[j].z, h2, lo2); bsplit(q4[j].w, h3, lo3);
            *(uint2*)(smem + AQH + row * LDP * 2 + c4 * 8) =
                make_uint2(pack_bf16x2(h0, h1), pack_bf16x2(h2, h3));
            *(uint2*)(smem + AQL + row * LDP * 2 + c4 * 8) =
                make_uint2(pack_bf16x2(lo0, lo1), pack_bf16x2(lo2, lo3));
        }
#pragma unroll
        for (int j = 0; j < 8; j++) {
            int p = vpb + 4 * j;
            float h0, lo0, h1, lo1;
            bsplit(vv[2 * j + 0], h0, lo0);
            bsplit(vv[2 * j + 1], h1, lo1);
            *(uint32_t*)(smem + AVH + vd * LDP * 2 + p * 4) = pack_bf16x2(h0, h1);
            *(uint32_t*)(smem + AVL + vd * LDP * 2 + p * 4) = pack_bf16x2(lo0, lo1);
        }
        if (tid < 64) msp[tid] = mk;
        __syncthreads();

        // ---- prefetch next step ----
        if (step + 1 < 64) {
            int t0n = (step + 1) * 64;
#pragma unroll
            for (int j = 0; j < 4; j++) {
                int idx = tid + 256 * j;
                q4[j] = *(const float4*)&Q[(size_t)(t0n + (idx >> 4)) * DD + (idx & 15) * 4];
            }
#pragma unroll
            for (int j = 0; j < 8; j++) {
                int p = vpb + 4 * j;
                vv[2 * j + 0] = V[(size_t)(t0n + 2 * p + 0) * DD + vd];
                vv[2 * j + 1] = V[(size_t)(t0n + 2 * p + 1) * DD + vd];
            }
            if (tid < 64) mk = mask[b * SS + t0n + tid];
        }

        // ---- MMA1: S(16x64) = K(16x64) . Q^T, 3-pass split ----
        float sacc[8][4];
#pragma unroll
        for (int nt = 0; nt < 8; nt++)
#pragma unroll
            for (int e = 0; e < 4; e++) sacc[nt][e] = 0.0f;

#pragma unroll
        for (int pass = 0; pass < 3; pass++) {
            const uint32_t(*Af)[4] = (pass == 2) ? Klf : Khf;
            uint32_t Qbase = sb + ((pass == 1) ? AQL : AQH);
#pragma unroll
            for (int kc = 0; kc < 4; kc++) {
#pragma unroll
                for (int p = 0; p < 4; p++) {
                    uint32_t bq[4];
                    ldsm_x4(bq, b2_addr_ld(Qbase, p * 16, kc * 16, lane, LDP));
                    mma16816(sacc[2 * p + 0], Af[kc], bq + 0);
                    mma16816(sacc[2 * p + 1], Af[kc], bq + 2);
                }
            }
        }

        // ---- masked exp (no max subtraction; scores bounded) ----
#pragma unroll
        for (int nt = 0; nt < 8; nt++) {
            int m0c = msp[nt * 8 + tig * 2 + 0];
            int m1c = msp[nt * 8 + tig * 2 + 1];
            float p0 = m0c ? __expf(sacc[nt][0] * 0.125f) : 0.0f;
            float p1 = m1c ? __expf(sacc[nt][1] * 0.125f) : 0.0f;
            float p2 = m0c ? __expf(sacc[nt][2] * 0.125f) : 0.0f;
            float p3 = m1c ? __expf(sacc[nt][3] * 0.125f) : 0.0f;
            sacc[nt][0] = p0; sacc[nt][1] = p1;
            sacc[nt][2] = p2; sacc[nt][3] = p3;
            l0 += p0 + p1;
            l1 += p2 + p3;
        }

        // ---- build P A-fragments hi/lo directly from accumulators ----
        // C frag (c0,c1)=row gid cols 2tig,2tig+1 ; (c2,c3)=row gid+8.
        // A frag m16k16: a0=(gid,k0pair) a1=(gid+8,k0pair) a2=(gid,k0pair+8) a3=(gid+8,+8)
        uint32_t Ph[4][4], Pl[4][4];
#pragma unroll
        for (int kc = 0; kc < 4; kc++) {
            int t0 = 2 * kc, t1 = 2 * kc + 1;
            float h00, l00, h01, l01, h02, l02, h03, l03;
            float h10, l10, h11, l11, h12, l12, h13, l13;
            bsplit(sacc[t0][0], h00, l00); bsplit(sacc[t0][1], h01, l01);
            bsplit(sacc[t0][2], h02, l02); bsplit(sacc[t0][3], h03, l03);
            bsplit(sacc[t1][0], h10, l10); bsplit(sacc[t1][1], h11, l11);
            bsplit(sacc[t1][2], h12, l12); bsplit(sacc[t1][3], h13, l13);
            Ph[kc][0] = pack_bf16x2(h00, h01); Ph[kc][1] = pack_bf16x2(h02, h03);
            Ph[kc][2] = pack_bf16x2(h10, h11); Ph[kc][3] = pack_bf16x2(h12, h13);
            Pl[kc][0] = pack_bf16x2(l00, l01); Pl[kc][1] = pack_bf16x2(l02, l03);
            Pl[kc][2] = pack_bf16x2(l10, l11); Pl[kc][3] = pack_bf16x2(l12, l13);
        }

        // ---- MMA2: O(16x64) += P(16x64) . V, 3-pass split ----
#pragma unroll
        for (int pass = 0; pass < 3; pass++) {
            const uint32_t(*Af)[4] = (pass == 2) ? Pl : Ph;
            uint32_t Vbase = sb + ((pass == 1) ? AVL : AVH);
#pragma unroll
            for (int kc = 0; kc < 4; kc++) {
#pragma unroll
                for (int p = 0; p < 4; p++) {
                    uint32_t bv[4];
                    ldsm_x4(bv, b2_addr_ld(Vbase, p * 16, kc * 16, lane, LDP));
                    mma16816(oacc[2 * p + 0], Af[kc], bv + 0);
                    mma16816(oacc[2 * p + 1], Af[kc], bv + 2);
                }
            }
        }
        __syncthreads();
    }

    // ---- epilogue: warp-local l reduce, normalize, store ----
    l0 += __shfl_xor_sync(0xffffffffu, l0, 1);
    l0 += __shfl_xor_sync(0xffffffffu, l0, 2);
    l1 += __shfl_xor_sync(0xffffffffu, l1, 1);
    l1 += __shfl_xor_sync(0xffffffffu, l1, 2);
    float inv0 = 1.0f / l0;
    float inv1 = 1.0f / l1;

    int row0 = r0 + wid * 16 + gid;
    int row1 = row0 + 8;
#pragma unroll
    for (int nt = 0; nt < 8; nt++) {
        int d0 = nt * 8 + tig * 2;
        *(float2*)&out[((size_t)b * SS + row0) * DD + d0] =
            make_float2(oacc[nt][0] * inv0, oacc[nt][1] * inv0);
        *(float2*)&out[((size_t)b * SS + row1) * DD + d0] =
            make_float2(oacc[nt][2] * inv1, oacc[nt][3] * inv1);
    }
}

extern "C" void kernel_launch(void* const* d_in, const int* in_sizes, int n_in,
                              void* d_out, int out_size) {
    const float* x    = (const float*)d_in[0];
    const int*   mask = (const int*)d_in[1];
    const float* Wk   = (const float*)d_in[2];
    const float* Wq   = (const float*)d_in[3];
    const float* Wv   = (const float*)d_in[4];
    float* out = (float*)d_out;

    cudaFuncSetAttribute(proj_mma_kernel,
                         cudaFuncAttributeMaxDynamicSharedMemorySize, PSMEM);
    proj_mma_kernel<<<128, 256, PSMEM>>>(x, Wk, Wq, Wv);

    cudaFuncSetAttribute(attn_mma_kernel,
                         cudaFuncAttributeMaxDynamicSharedMemorySize, ASMEM);
    dim3 grid(32, 4);
    attn_mma_kernel<<<grid, 256, ASMEM>>>(mask, out);
}

// round 7
// speedup vs baseline: 2.8659x; 1.1087x over previous
#include <cuda_runtime.h>
#include <cuda_bf16.h>
#include <cstdint>

#define BB 4
#define SS 4096
#define HH 1024
#define DD 64

// Pre-split bf16 projection outputs (written by proj, read by attn)
__device__ __align__(16) __nv_bfloat16 g_Khi[BB * SS * DD];
__device__ __align__(16) __nv_bfloat16 g_Klo[BB * SS * DD];
__device__ __align__(16) __nv_bfloat16 g_Qhi[BB * SS * DD];
__device__ __align__(16) __nv_bfloat16 g_Qlo[BB * SS * DD];
__device__ __align__(16) __nv_bfloat16 g_VThi[BB * DD * SS];  // transposed [b][d][t]
__device__ __align__(16) __nv_bfloat16 g_VTlo[BB * DD * SS];

// ===========================================================================
// Common mma.sync helpers (plain sm_103 — no tcgen05)
// ===========================================================================
__device__ __forceinline__ uint32_t smem_u32_of(const void* p) {
    uint32_t addr;
    asm("{ .reg .u64 tmp; cvta.to.shared.u64 tmp, %1; cvt.u32.u64 %0, tmp; }"
        : "=r"(addr) : "l"(p));
    return addr;
}

__device__ __forceinline__ void ldsm_x4(uint32_t* r, uint32_t addr) {
    asm volatile("ldmatrix.sync.aligned.m8n8.x4.shared.b16 {%0,%1,%2,%3}, [%4];"
                 : "=r"(r[0]), "=r"(r[1]), "=r"(r[2]), "=r"(r[3]) : "r"(addr));
}
__device__ __forceinline__ void mma16816(float* d, const uint32_t* a,
                                         const uint32_t* b) {
    asm volatile(
        "mma.sync.aligned.m16n8k16.row.col.f32.bf16.bf16.f32 "
        "{%0,%1,%2,%3}, {%4,%5,%6,%7}, {%8,%9}, {%0,%1,%2,%3};"
        : "+f"(d[0]), "+f"(d[1]), "+f"(d[2]), "+f"(d[3])
        : "r"(a[0]), "r"(a[1]), "r"(a[2]), "r"(a[3]), "r"(b[0]), "r"(b[1]));
}

__device__ __forceinline__ uint32_t pack_bf16x2(float lo, float hi) {
    __nv_bfloat162 t = __floats2bfloat162_rn(lo, hi);
    return *(uint32_t*)&t;
}
__device__ __forceinline__ void bsplit(float v, float& h, float& l) {
    __nv_bfloat16 hb = __float2bfloat16(v);
    h = __bfloat162float(hb);
    l = v - h;
}

__device__ __forceinline__ void cp_async16(uint32_t smem_addr, const void* gptr) {
    asm volatile("cp.async.ca.shared.global [%0], [%1], 16;"
                 :: "r"(smem_addr), "l"(gptr) : "memory");
}
#define CP_COMMIT() asm volatile("cp.async.commit_group;" ::: "memory")
#define CP_WAIT(n)  asm volatile("cp.async.wait_group %0;" :: "n"(n) : "memory")

// A-fragment ldmatrix.x4 address (16x16 tile at row0,col0), row stride ld bf16
__device__ __forceinline__ uint32_t a_addr_ld(uint32_t base, int row0, int col0,
                                              int lane, int ld) {
    int t = lane >> 3, ri = lane & 7;
    int row = row0 + ri + ((t & 1) << 3);
    int col = col0 + ((t >> 1) << 3);
    return base + (uint32_t)(row * ld + col) * 2;
}
// B-pair ldmatrix.x4 (two adjacent n8k16 tiles)
__device__ __forceinline__ uint32_t b2_addr_ld(uint32_t base, int n0, int k0,
                                               int lane, int ld) {
    int row = n0 + ((lane >> 4) << 3) + (lane & 7);
    int col = k0 + (((lane >> 3) & 1) << 3);
    return base + (uint32_t)(row * ld + col) * 2;
}

// ===========================================================================
// Projection via mma.sync bf16 3-pass split; epilogue writes pre-split
// bf16 hi/lo arrays (K,Q row-major; V transposed).
// ===========================================================================
#define PLDP 40
#define PX_HI 0
#define PX_LO (PX_HI + 128 * PLDP * 2)
#define PW_HI (PX_LO + 128 * PLDP * 2)
#define PW_LO (PW_HI + 192 * PLDP * 2)
#define PSMEM (PW_LO + 192 * PLDP * 2)

__global__ void __launch_bounds__(256) proj_mma_kernel(const float* __restrict__ x,
                                                       const float* __restrict__ Wk,
                                                       const float* __restrict__ Wq,
                                                       const float* __restrict__ Wv) {
    extern __shared__ char smem[];
    const uint32_t sb = smem_u32_of(smem);

    const int tid = threadIdx.x;
    const int wid = tid >> 5;
    const int lane = tid & 31;
    const int warp_m = wid & 3;
    const int warp_n = wid >> 2;
    const int m0 = blockIdx.x * 128;

    float4 xr[4], wr[6];

#pragma unroll
    for (int j = 0; j < 4; j++) {
        int idx = tid + 256 * j;
        xr[j] = *(const float4*)&x[(size_t)(m0 + (idx >> 3)) * HH + (idx & 7) * 4];
    }
#pragma unroll
    for (int j = 0; j < 6; j++) {
        int idx = tid + 256 * j;
        int row = idx >> 3;
        const float* W = (row < 64) ? Wk : ((row < 128) ? Wq : Wv);
        wr[j] = *(const float4*)&W[(size_t)(row & 63) * HH + (idx & 7) * 4];
    }

    float acc[2][12][4];
#pragma unroll
    for (int mt = 0; mt < 2; mt++)
#pragma unroll
        for (int nn = 0; nn < 12; nn++)
#pragma unroll
            for (int e = 0; e < 4; e++) acc[mt][nn][e] = 0.0f;

#pragma unroll 1
    for (int it = 0; it < 32; it++) {
#pragma unroll
        for (int j = 0; j < 4; j++) {
            int idx = tid + 256 * j;
            int row = idx >> 3, c4 = idx & 7;
            float h0, l0, h1, l1, h2, l2, h3, l3;
            bsplit(xr[j].x, h0, l0); bsplit(xr[j].y, h1, l1);
            bsplit(xr[j].z, h2, l2); bsplit(xr[j].w, h3, l3);
            *(uint2*)(smem + PX_HI + row * PLDP * 2 + c4 * 8) =
                make_uint2(pack_bf16x2(h0, h1), pack_bf16x2(h2, h3));
            *(uint2*)(smem + PX_LO + row * PLDP * 2 + c4 * 8) =
                make_uint2(pack_bf16x2(l0, l1), pack_bf16x2(l2, l3));
        }
#pragma unroll
        for (int j = 0; j < 6; j++) {
            int idx = tid + 256 * j;
            int row = idx >> 3, c4 = idx & 7;
            float h0, l0, h1, l1, h2, l2, h3, l3;
            bsplit(wr[j].x, h0, l0); bsplit(wr[j].y, h1, l1);
            bsplit(wr[j].z, h2, l2); bsplit(wr[j].w, h3, l3);
            *(uint2*)(smem + PW_HI + row * PLDP * 2 + c4 * 8) =
                make_uint2(pack_bf16x2(h0, h1), pack_bf16x2(h2, h3));
            *(uint2*)(smem + PW_LO + row * PLDP * 2 + c4 * 8) =
                make_uint2(pack_bf16x2(l0, l1), pack_bf16x2(l2, l3));
        }
        __syncthreads();

        if (it + 1 < 32) {
            int k0 = (it + 1) * 32;
#pragma unroll
            for (int j = 0; j < 4; j++) {
                int idx = tid + 256 * j;
                xr[j] = *(const float4*)&x[(size_t)(m0 + (idx >> 3)) * HH + k0 + (idx & 7) * 4];
            }
#pragma unroll
            for (int j = 0; j < 6; j++) {
                int idx = tid + 256 * j;
                int row = idx >> 3;
                const float* W = (row < 64) ? Wk : ((row < 128) ? Wq : Wv);
                wr[j] = *(const float4*)&W[(size_t)(row & 63) * HH + k0 + (idx & 7) * 4];
            }
        }

#pragma unroll
        for (int kc = 0; kc < 2; kc++) {
            uint32_t ah[2][4], al[2][4];
#pragma unroll
            for (int mt = 0; mt < 2; mt++) {
                ldsm_x4(ah[mt], a_addr_ld(sb + PX_HI, warp_m * 32 + mt * 16, kc * 16, lane, PLDP));
                ldsm_x4(al[mt], a_addr_ld(sb + PX_LO, warp_m * 32 + mt * 16, kc * 16, lane, PLDP));
            }
#pragma unroll
            for (int nh = 0; nh < 2; nh++) {
                uint32_t bh[6][2], bl[6][2];
#pragma unroll
                for (int pp = 0; pp < 3; pp++) {
                    uint32_t tmp[4];
                    int n0 = warp_n * 96 + nh * 48 + pp * 16;
                    ldsm_x4(tmp, b2_addr_ld(sb + PW_HI, n0, kc * 16, lane, PLDP));
                    bh[2 * pp][0] = tmp[0]; bh[2 * pp][1] = tmp[1];
                    bh[2 * pp + 1][0] = tmp[2]; bh[2 * pp + 1][1] = tmp[3];
                    ldsm_x4(tmp, b2_addr_ld(sb + PW_LO, n0, kc * 16, lane, PLDP));
                    bl[2 * pp][0] = tmp[0]; bl[2 * pp][1] = tmp[1];
                    bl[2 * pp + 1][0] = tmp[2]; bl[2 * pp + 1][1] = tmp[3];
                }
#pragma unroll
                for (int mt = 0; mt < 2; mt++)
#pragma unroll
                    for (int nt = 0; nt < 6; nt++) {
                        float* d = acc[mt][nh * 6 + nt];
                        mma16816(d, ah[mt], bh[nt]);
                        mma16816(d, ah[mt], bl[nt]);
                        mma16816(d, al[mt], bh[nt]);
                    }
            }
        }
        __syncthreads();
    }

    // ---- epilogue: split to bf16 hi/lo, K/Q row-major, V transposed ----
#pragma unroll
    for (int mt = 0; mt < 2; mt++)
#pragma unroll
        for (int rp = 0; rp < 2; rp++) {
            int row = m0 + warp_m * 32 + mt * 16 + rp * 8 + (lane >> 2);
            int bb_ = row >> 12, t = row & 4095;
#pragma unroll
            for (int nn = 0; nn < 12; nn++) {
                int n = warp_n * 96 + nn * 8 + (lane & 3) * 2;
                int which = n >> 6, d = n & 63;
                float v0 = acc[mt][nn][rp * 2 + 0];
                float v1 = acc[mt][nn][rp * 2 + 1];
                float h0, l0, h1, l1;
                bsplit(v0, h0, l0);
                bsplit(v1, h1, l1);
                if (which == 2) {
                    size_t base = (size_t)bb_ * DD * SS;
                    g_VThi[base + (size_t)d * SS + t] = __float2bfloat16(h0);
                    g_VThi[base + (size_t)(d + 1) * SS + t] = __float2bfloat16(h1);
                    g_VTlo[base + (size_t)d * SS + t] = __float2bfloat16(l0);
                    g_VTlo[base + (size_t)(d + 1) * SS + t] = __float2bfloat16(l1);
                } else {
                    __nv_bfloat16* Bh = which ? g_Qhi : g_Khi;
                    __nv_bfloat16* Bl = which ? g_Qlo : g_Klo;
                    size_t off = (size_t)row * DD + d;
                    *(uint32_t*)&Bh[off] = pack_bf16x2(h0, h1);
                    *(uint32_t*)&Bl[off] = pack_bf16x2(l0, l1);
                }
            }
        }
}

// ===========================================================================
// Attention R7: cp.async double-buffered tiles (pre-split bf16 from gmem),
// no conversion in loop, mask preloaded once, K frags register-resident.
// ===========================================================================
#define LDP 72                              // bf16/row -> 144 B rows
#define TILE_B (64 * LDP * 2)               // 9216 bytes per 64x64 tile
#define BUF_B  (4 * TILE_B)                 // Qhi,Qlo,Vhi,Vlo
#define AMSK   (2 * BUF_B)                  // 73728
#define ASMEM  (AMSK + SS * 4)              // + 16 KB mask

__global__ void __launch_bounds__(256) attn_mma_kernel(const int* __restrict__ mask,
                                                       float* __restrict__ out) {
    extern __shared__ char smem[];
    const uint32_t sb = smem_u32_of(smem);

    const int tid = threadIdx.x;
    const int wid = tid >> 5;
    const int lane = tid & 31;
    const int gid = lane >> 2;
    const int tig = lane & 3;
    const int b = blockIdx.y;
    const int r0 = blockIdx.x * 128;

    const __nv_bfloat16* Khi = g_Khi + (size_t)b * SS * DD;
    const __nv_bfloat16* Klo = g_Klo + (size_t)b * SS * DD;
    const __nv_bfloat16* Qhi = g_Qhi + (size_t)b * SS * DD;
    const __nv_bfloat16* Qlo = g_Qlo + (size_t)b * SS * DD;
    const __nv_bfloat16* VThi = g_VThi + (size_t)b * DD * SS;
    const __nv_bfloat16* VTlo = g_VTlo + (size_t)b * DD * SS;

    const int* msk = (const int*)(smem + AMSK);

    // ---- stage K (hi at buf0+0, lo at buf0+18432) + mask, via cp.async ----
#pragma unroll
    for (int j = 0; j < 4; j++) {
        int chunk = tid + 256 * j;          // 0..1023
        int row = chunk >> 3, c8 = chunk & 7;
        uint32_t dst = sb + (uint32_t)(row * 144 + c8 * 16);
        cp_async16(dst, Khi + (size_t)(r0 + row) * DD + c8 * 8);
        cp_async16(dst + 18432, Klo + (size_t)(r0 + row) * DD + c8 * 8);
        cp_async16(sb + AMSK + chunk * 16, mask + b * SS + chunk * 4);
    }
    CP_COMMIT();
    CP_WAIT(0);
    __syncthreads();

    uint32_t Khf[4][4], Klf[4][4];
#pragma unroll
    for (int kc = 0; kc < 4; kc++) {
        ldsm_x4(Khf[kc], a_addr_ld(sb, wid * 16, kc * 16, lane, LDP));
        ldsm_x4(Klf[kc], a_addr_ld(sb + 18432, wid * 16, kc * 16, lane, LDP));
    }
    __syncthreads();   // K staging area becomes buffer 0

    // ---- issue step-0 tiles into buf0 ----
#pragma unroll
    for (int c = 0; c < 2; c++) {
        int chunk = tid + c * 256;          // 0..511
        int row = chunk >> 3, c8 = chunk & 7;
        uint32_t dst = sb + (uint32_t)(row * 144 + c8 * 16);
        cp_async16(dst, Qhi + (size_t)row * DD + c8 * 8);
        cp_async16(dst + TILE_B, Qlo + (size_t)row * DD + c8 * 8);
        cp_async16(dst + 2 * TILE_B, VThi + (size_t)row * SS + c8 * 8);
        cp_async16(dst + 3 * TILE_B, VTlo + (size_t)row * SS + c8 * 8);
    }
    CP_COMMIT();

    float oacc[8][4];
#pragma unroll
    for (int nt = 0; nt < 8; nt++)
#pragma unroll
        for (int e = 0; e < 4; e++) oacc[nt][e] = 0.0f;
    float l0 = 0.0f, l1 = 0.0f;

#pragma unroll 1
    for (int step = 0; step < 64; step++) {
        // issue next step's tiles (double buffer)
        if (step + 1 < 64) {
            int t0n = (step + 1) * 64;
            uint32_t bufn = sb + ((step + 1) & 1) * BUF_B;
#pragma unroll
            for (int c = 0; c < 2; c++) {
                int chunk = tid + c * 256;
                int row = chunk >> 3, c8 = chunk & 7;
                uint32_t dst = bufn + (uint32_t)(row * 144 + c8 * 16);
                cp_async16(dst, Qhi + (size_t)(t0n + row) * DD + c8 * 8);
                cp_async16(dst + TILE_B, Qlo + (size_t)(t0n + row) * DD + c8 * 8);
                cp_async16(dst + 2 * TILE_B, VThi + (size_t)row * SS + t0n + c8 * 8);
                cp_async16(dst + 3 * TILE_B, VTlo + (size_t)row * SS + t0n + c8 * 8);
            }
            CP_COMMIT();
            CP_WAIT(1);
        } else {
            CP_WAIT(0);
        }
        __syncthreads();

        uint32_t buf = sb + (step & 1) * BUF_B;
        uint32_t Qh = buf, Ql = buf + TILE_B;
        uint32_t Vh = buf + 2 * TILE_B, Vl = buf + 3 * TILE_B;

        // ---- MMA1: S(16x64) = K . Q^T, 3-pass split ----
        float sacc[8][4];
#pragma unroll
        for (int nt = 0; nt < 8; nt++)
#pragma unroll
            for (int e = 0; e < 4; e++) sacc[nt][e] = 0.0f;

#pragma unroll
        for (int pass = 0; pass < 3; pass++) {
            const uint32_t(*Af)[4] = (pass == 2) ? Klf : Khf;
            uint32_t Qbase = (pass == 1) ? Ql : Qh;
#pragma unroll
            for (int kc = 0; kc < 4; kc++) {
#pragma unroll
                for (int p = 0; p < 4; p++) {
                    uint32_t bq[4];
                    ldsm_x4(bq, b2_addr_ld(Qbase, p * 16, kc * 16, lane, LDP));
                    mma16816(sacc[2 * p + 0], Af[kc], bq + 0);
                    mma16816(sacc[2 * p + 1], Af[kc], bq + 2);
                }
            }
        }

        // ---- masked exp (no max subtraction; scores bounded) ----
        const int mbase = step * 64;
#pragma unroll
        for (int nt = 0; nt < 8; nt++) {
            int m0c = msk[mbase + nt * 8 + tig * 2 + 0];
            int m1c = msk[mbase + nt * 8 + tig * 2 + 1];
            float p0 = m0c ? __expf(sacc[nt][0] * 0.125f) : 0.0f;
            float p1 = m1c ? __expf(sacc[nt][1] * 0.125f) : 0.0f;
            float p2 = m0c ? __expf(sacc[nt][2] * 0.125f) : 0.0f;
            float p3 = m1c ? __expf(sacc[nt][3] * 0.125f) : 0.0f;
            sacc[nt][0] = p0; sacc[nt][1] = p1;
            sacc[nt][2] = p2; sacc[nt][3] = p3;
            l0 += p0 + p1;
            l1 += p2 + p3;
        }

        // ---- build P A-fragments hi/lo from accumulators ----
        uint32_t Ph[4][4], Pl[4][4];
#pragma unroll
        for (int kc = 0; kc < 4; kc++) {
            int t0 = 2 * kc, t1 = 2 * kc + 1;
            float h00, l00, h01, l01, h02, l02, h03, l03;
            float h10, l10, h11, l11, h12, l12, h13, l13;
            bsplit(sacc[t0][0], h00, l00); bsplit(sacc[t0][1], h01, l01);
            bsplit(sacc[t0][2], h02, l02); bsplit(sacc[t0][3], h03, l03);
            bsplit(sacc[t1][0], h10, l10); bsplit(sacc[t1][1], h11, l11);
            bsplit(sacc[t1][2], h12, l12); bsplit(sacc[t1][3], h13, l13);
            Ph[kc][0] = pack_bf16x2(h00, h01); Ph[kc][1] = pack_bf16x2(h02, h03);
            Ph[kc][2] = pack_bf16x2(h10, h11); Ph[kc][3] = pack_bf16x2(h12, h13);
            Pl[kc][0] = pack_bf16x2(l00, l01); Pl[kc][1] = pack_bf16x2(l02, l03);
            Pl[kc][2] = pack_bf16x2(l10, l11); Pl[kc][3] = pack_bf16x2(l12, l13);
        }

        // ---- MMA2: O(16x64) += P . V, 3-pass split ----
#pragma unroll
        for (int pass = 0; pass < 3; pass++) {
            const uint32_t(*Af)[4] = (pass == 2) ? Pl : Ph;
            uint32_t Vbase = (pass == 1) ? Vl : Vh;
#pragma unroll
            for (int kc = 0; kc < 4; kc++) {
#pragma unroll
                for (int p = 0; p < 4; p++) {
                    uint32_t bv[4];
                    ldsm_x4(bv, b2_addr_ld(Vbase, p * 16, kc * 16, lane, LDP));
                    mma16816(oacc[2 * p + 0], Af[kc], bv + 0);
                    mma16816(oacc[2 * p + 1], Af[kc], bv + 2);
                }
            }
        }
        __syncthreads();   // compute done before this buffer is refilled
    }

    // ---- epilogue: warp-local l reduce, normalize, store ----
    l0 += __shfl_xor_sync(0xffffffffu, l0, 1);
    l0 += __shfl_xor_sync(0xffffffffu, l0, 2);
    l1 += __shfl_xor_sync(0xffffffffu, l1, 1);
    l1 += __shfl_xor_sync(0xffffffffu, l1, 2);
    float inv0 = 1.0f / l0;
    float inv1 = 1.0f / l1;

    int row0 = r0 + wid * 16 + gid;
    int row1 = row0 + 8;
#pragma unroll
    for (int nt = 0; nt < 8; nt++) {
        int d0 = nt * 8 + tig * 2;
        *(float2*)&out[((size_t)b * SS + row0) * DD + d0] =
            make_float2(oacc[nt][0] * inv0, oacc[nt][1] * inv0);
        *(float2*)&out[((size_t)b * SS + row1) * DD + d0] =
            make_float2(oacc[nt][2] * inv1, oacc[nt][3] * inv1);
    }
}

extern "C" void kernel_launch(void* const* d_in, const int* in_sizes, int n_in,
                              void* d_out, int out_size) {
    const float* x    = (const float*)d_in[0];
    const int*   mask = (const int*)d_in[1];
    const float* Wk   = (const float*)d_in[2];
    const float* Wq   = (const float*)d_in[3];
    const float* Wv   = (const float*)d_in[4];
    float* out = (float*)d_out;

    cudaFuncSetAttribute(proj_mma_kernel,
                         cudaFuncAttributeMaxDynamicSharedMemorySize, PSMEM);
    proj_mma_kernel<<<128, 256, PSMEM>>>(x, Wk, Wq, Wv);

    cudaFuncSetAttribute(attn_mma_kernel,
                         cudaFuncAttributeMaxDynamicSharedMemorySize, ASMEM);
    dim3 grid(32, 4);
    attn_mma_kernel<<<grid, 256, ASMEM>>>(mask, out);
}

// round 8
// speedup vs baseline: 3.2004x; 1.1167x over previous
#include <cuda_runtime.h>
#include <cuda_bf16.h>
#include <cstdint>

#define BB 4
#define SS 4096
#define HH 1024
#define DD 64

// Pre-split bf16 projection outputs (written by proj, read by attn)
__device__ __align__(16) __nv_bfloat16 g_Khi[BB * SS * DD];
__device__ __align__(16) __nv_bfloat16 g_Klo[BB * SS * DD];
__device__ __align__(16) __nv_bfloat16 g_Qhi[BB * SS * DD];
__device__ __align__(16) __nv_bfloat16 g_Qlo[BB * SS * DD];
__device__ __align__(16) __nv_bfloat16 g_VThi[BB * DD * SS];  // transposed [b][d][t]
__device__ __align__(16) __nv_bfloat16 g_VTlo[BB * DD * SS];

// ===========================================================================
// Common mma.sync helpers (plain sm_103 — no tcgen05)
// ===========================================================================
__device__ __forceinline__ uint32_t smem_u32_of(const void* p) {
    uint32_t addr;
    asm("{ .reg .u64 tmp; cvta.to.shared.u64 tmp, %1; cvt.u32.u64 %0, tmp; }"
        : "=r"(addr) : "l"(p));
    return addr;
}

__device__ __forceinline__ void ldsm_x4(uint32_t* r, uint32_t addr) {
    asm volatile("ldmatrix.sync.aligned.m8n8.x4.shared.b16 {%0,%1,%2,%3}, [%4];"
                 : "=r"(r[0]), "=r"(r[1]), "=r"(r[2]), "=r"(r[3]) : "r"(addr));
}
__device__ __forceinline__ void mma16816(float* d, const uint32_t* a,
                                         const uint32_t* b) {
    asm volatile(
        "mma.sync.aligned.m16n8k16.row.col.f32.bf16.bf16.f32 "
        "{%0,%1,%2,%3}, {%4,%5,%6,%7}, {%8,%9}, {%0,%1,%2,%3};"
        : "+f"(d[0]), "+f"(d[1]), "+f"(d[2]), "+f"(d[3])
        : "r"(a[0]), "r"(a[1]), "r"(a[2]), "r"(a[3]), "r"(b[0]), "r"(b[1]));
}

__device__ __forceinline__ uint32_t pack_bf16x2(float lo, float hi) {
    __nv_bfloat162 t = __floats2bfloat162_rn(lo, hi);
    return *(uint32_t*)&t;
}
__device__ __forceinline__ void bsplit(float v, float& h, float& l) {
    __nv_bfloat16 hb = __float2bfloat16(v);
    h = __bfloat162float(hb);
    l = v - h;
}

__device__ __forceinline__ void cp_async16(uint32_t smem_addr, const void* gptr) {
    asm volatile("cp.async.ca.shared.global [%0], [%1], 16;"
                 :: "r"(smem_addr), "l"(gptr) : "memory");
}
#define CP_COMMIT() asm volatile("cp.async.commit_group;" ::: "memory")
#define CP_WAIT(n)  asm volatile("cp.async.wait_group %0;" :: "n"(n) : "memory")

// A-fragment ldmatrix.x4 address (16x16 tile at row0,col0), row stride ld bf16
__device__ __forceinline__ uint32_t a_addr_ld(uint32_t base, int row0, int col0,
                                              int lane, int ld) {
    int t = lane >> 3, ri = lane & 7;
    int row = row0 + ri + ((t & 1) << 3);
    int col = col0 + ((t >> 1) << 3);
    return base + (uint32_t)(row * ld + col) * 2;
}
// B-pair ldmatrix.x4 (two adjacent n8k16 tiles)
__device__ __forceinline__ uint32_t b2_addr_ld(uint32_t base, int n0, int k0,
                                               int lane, int ld) {
    int row = n0 + ((lane >> 4) << 3) + (lane & 7);
    int col = k0 + (((lane >> 3) & 1) << 3);
    return base + (uint32_t)(row * ld + col) * 2;
}

// ===========================================================================
// Projection via mma.sync bf16 3-pass split; epilogue writes pre-split
// bf16 hi/lo arrays (K,Q row-major; V transposed). Unchanged from R7.
// ===========================================================================
#define PLDP 40
#define PX_HI 0
#define PX_LO (PX_HI + 128 * PLDP * 2)
#define PW_HI (PX_LO + 128 * PLDP * 2)
#define PW_LO (PW_HI + 192 * PLDP * 2)
#define PSMEM (PW_LO + 192 * PLDP * 2)

__global__ void __launch_bounds__(256) proj_mma_kernel(const float* __restrict__ x,
                                                       const float* __restrict__ Wk,
                                                       const float* __restrict__ Wq,
                                                       const float* __restrict__ Wv) {
    extern __shared__ char smem[];
    const uint32_t sb = smem_u32_of(smem);

    const int tid = threadIdx.x;
    const int wid = tid >> 5;
    const int lane = tid & 31;
    const int warp_m = wid & 3;
    const int warp_n = wid >> 2;
    const int m0 = blockIdx.x * 128;

    float4 xr[4], wr[6];

#pragma unroll
    for (int j = 0; j < 4; j++) {
        int idx = tid + 256 * j;
        xr[j] = *(const float4*)&x[(size_t)(m0 + (idx >> 3)) * HH + (idx & 7) * 4];
    }
#pragma unroll
    for (int j = 0; j < 6; j++) {
        int idx = tid + 256 * j;
        int row = idx >> 3;
        const float* W = (row < 64) ? Wk : ((row < 128) ? Wq : Wv);
        wr[j] = *(const float4*)&W[(size_t)(row & 63) * HH + (idx & 7) * 4];
    }

    float acc[2][12][4];
#pragma unroll
    for (int mt = 0; mt < 2; mt++)
#pragma unroll
        for (int nn = 0; nn < 12; nn++)
#pragma unroll
            for (int e = 0; e < 4; e++) acc[mt][nn][e] = 0.0f;

#pragma unroll 1
    for (int it = 0; it < 32; it++) {
#pragma unroll
        for (int j = 0; j < 4; j++) {
            int idx = tid + 256 * j;
            int row = idx >> 3, c4 = idx & 7;
            float h0, l0, h1, l1, h2, l2, h3, l3;
            bsplit(xr[j].x, h0, l0); bsplit(xr[j].y, h1, l1);
            bsplit(xr[j].z, h2, l2); bsplit(xr[j].w, h3, l3);
            *(uint2*)(smem + PX_HI + row * PLDP * 2 + c4 * 8) =
                make_uint2(pack_bf16x2(h0, h1), pack_bf16x2(h2, h3));
            *(uint2*)(smem + PX_LO + row * PLDP * 2 + c4 * 8) =
                make_uint2(pack_bf16x2(l0, l1), pack_bf16x2(l2, l3));
        }
#pragma unroll
        for (int j = 0; j < 6; j++) {
            int idx = tid + 256 * j;
            int row = idx >> 3, c4 = idx & 7;
            float h0, l0, h1, l1, h2, l2, h3, l3;
            bsplit(wr[j].x, h0, l0); bsplit(wr[j].y, h1, l1);
            bsplit(wr[j].z, h2, l2); bsplit(wr[j].w, h3, l3);
            *(uint2*)(smem + PW_HI + row * PLDP * 2 + c4 * 8) =
                make_uint2(pack_bf16x2(h0, h1), pack_bf16x2(h2, h3));
            *(uint2*)(smem + PW_LO + row * PLDP * 2 + c4 * 8) =
                make_uint2(pack_bf16x2(l0, l1), pack_bf16x2(l2, l3));
        }
        __syncthreads();

        if (it + 1 < 32) {
            int k0 = (it + 1) * 32;
#pragma unroll
            for (int j = 0; j < 4; j++) {
                int idx = tid + 256 * j;
                xr[j] = *(const float4*)&x[(size_t)(m0 + (idx >> 3)) * HH + k0 + (idx & 7) * 4];
            }
#pragma unroll
            for (int j = 0; j < 6; j++) {
                int idx = tid + 256 * j;
                int row = idx >> 3;
                const float* W = (row < 64) ? Wk : ((row < 128) ? Wq : Wv);
                wr[j] = *(const float4*)&W[(size_t)(row & 63) * HH + k0 + (idx & 7) * 4];
            }
        }

#pragma unroll
        for (int kc = 0; kc < 2; kc++) {
            uint32_t ah[2][4], al[2][4];
#pragma unroll
            for (int mt = 0; mt < 2; mt++) {
                ldsm_x4(ah[mt], a_addr_ld(sb + PX_HI, warp_m * 32 + mt * 16, kc * 16, lane, PLDP));
                ldsm_x4(al[mt], a_addr_ld(sb + PX_LO, warp_m * 32 + mt * 16, kc * 16, lane, PLDP));
            }
#pragma unroll
            for (int nh = 0; nh < 2; nh++) {
                uint32_t bh[6][2], bl[6][2];
#pragma unroll
                for (int pp = 0; pp < 3; pp++) {
                    uint32_t tmp[4];
                    int n0 = warp_n * 96 + nh * 48 + pp * 16;
                    ldsm_x4(tmp, b2_addr_ld(sb + PW_HI, n0, kc * 16, lane, PLDP));
                    bh[2 * pp][0] = tmp[0]; bh[2 * pp][1] = tmp[1];
                    bh[2 * pp + 1][0] = tmp[2]; bh[2 * pp + 1][1] = tmp[3];
                    ldsm_x4(tmp, b2_addr_ld(sb + PW_LO, n0, kc * 16, lane, PLDP));
                    bl[2 * pp][0] = tmp[0]; bl[2 * pp][1] = tmp[1];
                    bl[2 * pp + 1][0] = tmp[2]; bl[2 * pp + 1][1] = tmp[3];
                }
#pragma unroll
                for (int mt = 0; mt < 2; mt++)
#pragma unroll
                    for (int nt = 0; nt < 6; nt++) {
                        float* d = acc[mt][nh * 6 + nt];
                        mma16816(d, ah[mt], bh[nt]);
                        mma16816(d, ah[mt], bl[nt]);
                        mma16816(d, al[mt], bh[nt]);
                    }
            }
        }
        __syncthreads();
    }

    // ---- epilogue: split to bf16 hi/lo, K/Q row-major, V transposed ----
#pragma unroll
    for (int mt = 0; mt < 2; mt++)
#pragma unroll
        for (int rp = 0; rp < 2; rp++) {
            int row = m0 + warp_m * 32 + mt * 16 + rp * 8 + (lane >> 2);
            int bb_ = row >> 12, t = row & 4095;
#pragma unroll
            for (int nn = 0; nn < 12; nn++) {
                int n = warp_n * 96 + nn * 8 + (lane & 3) * 2;
                int which = n >> 6, d = n & 63;
                float v0 = acc[mt][nn][rp * 2 + 0];
                float v1 = acc[mt][nn][rp * 2 + 1];
                float h0, l0, h1, l1;
                bsplit(v0, h0, l0);
                bsplit(v1, h1, l1);
                if (which == 2) {
                    size_t base = (size_t)bb_ * DD * SS;
                    g_VThi[base + (size_t)d * SS + t] = __float2bfloat16(h0);
                    g_VThi[base + (size_t)(d + 1) * SS + t] = __float2bfloat16(h1);
                    g_VTlo[base + (size_t)d * SS + t] = __float2bfloat16(l0);
                    g_VTlo[base + (size_t)(d + 1) * SS + t] = __float2bfloat16(l1);
                } else {
                    __nv_bfloat16* Bh = which ? g_Qhi : g_Khi;
                    __nv_bfloat16* Bl = which ? g_Qlo : g_Klo;
                    size_t off = (size_t)row * DD + d;
                    *(uint32_t*)&Bh[off] = pack_bf16x2(h0, h1);
                    *(uint32_t*)&Bl[off] = pack_bf16x2(l0, l1);
                }
            }
        }
}

// ===========================================================================
// Attention R8: 128-thread CTAs (4 warps, 64 K-rows), 2 CTAs/SM for
// decoupled barriers; B-load-major MMA loops (bq hi/lo loaded once per
// (kc,p), 3 split-pass MMAs issued against them).
// ===========================================================================
#define LDP 72                              // bf16/row -> 144 B rows
#define TILE_B (64 * LDP * 2)               // 9216 bytes per 64x64 tile
#define BUF_B  (4 * TILE_B)                 // Qhi,Qlo,Vhi,Vlo = 36864
#define AMSK   (2 * BUF_B)                  // 73728
#define ASMEM  (AMSK + SS * 4)              // + 16 KB mask = 90112

__global__ void __launch_bounds__(128, 2) attn_mma_kernel(const int* __restrict__ mask,
                                                          float* __restrict__ out) {
    extern __shared__ char smem[];
    const uint32_t sb = smem_u32_of(smem);

    const int tid = threadIdx.x;
    const int wid = tid >> 5;               // 0..3 -> rows wid*16..+16
    const int lane = tid & 31;
    const int gid = lane >> 2;
    const int tig = lane & 3;
    const int b = blockIdx.y;
    const int r0 = blockIdx.x * 64;

    const __nv_bfloat16* Khi = g_Khi + (size_t)b * SS * DD;
    const __nv_bfloat16* Klo = g_Klo + (size_t)b * SS * DD;
    const __nv_bfloat16* Qhi = g_Qhi + (size_t)b * SS * DD;
    const __nv_bfloat16* Qlo = g_Qlo + (size_t)b * SS * DD;
    const __nv_bfloat16* VThi = g_VThi + (size_t)b * DD * SS;
    const __nv_bfloat16* VTlo = g_VTlo + (size_t)b * DD * SS;

    const int* msk = (const int*)(smem + AMSK);

    // ---- stage K (hi at buf0+0, lo at buf0+9216) + mask, via cp.async ----
#pragma unroll
    for (int j = 0; j < 4; j++) {
        int chunk = tid + 128 * j;          // 0..511 (64 rows x 8)
        int row = chunk >> 3, c8 = chunk & 7;
        uint32_t dst = sb + (uint32_t)(row * 144 + c8 * 16);
        cp_async16(dst, Khi + (size_t)(r0 + row) * DD + c8 * 8);
        cp_async16(dst + TILE_B, Klo + (size_t)(r0 + row) * DD + c8 * 8);
    }
#pragma unroll
    for (int j = 0; j < 8; j++) {
        int chunk = tid + 128 * j;          // 0..1023 (16 KB / 16 B)
        cp_async16(sb + AMSK + chunk * 16, mask + b * SS + chunk * 4);
    }
    CP_COMMIT();
    CP_WAIT(0);
    __syncthreads();

    uint32_t Khf[4][4], Klf[4][4];
#pragma unroll
    for (int kc = 0; kc < 4; kc++) {
        ldsm_x4(Khf[kc], a_addr_ld(sb, wid * 16, kc * 16, lane, LDP));
        ldsm_x4(Klf[kc], a_addr_ld(sb + TILE_B, wid * 16, kc * 16, lane, LDP));
    }
    __syncthreads();   // K staging area becomes buffer 0

    // ---- issue step-0 tiles into buf0 ----
#pragma unroll
    for (int c = 0; c < 4; c++) {
        int chunk = tid + c * 128;          // 0..511
        int row = chunk >> 3, c8 = chunk & 7;
        uint32_t dst = sb + (uint32_t)(row * 144 + c8 * 16);
        cp_async16(dst, Qhi + (size_t)row * DD + c8 * 8);
        cp_async16(dst + TILE_B, Qlo + (size_t)row * DD + c8 * 8);
        cp_async16(dst + 2 * TILE_B, VThi + (size_t)row * SS + c8 * 8);
        cp_async16(dst + 3 * TILE_B, VTlo + (size_t)row * SS + c8 * 8);
    }
    CP_COMMIT();

    float oacc[8][4];
#pragma unroll
    for (int nt = 0; nt < 8; nt++)
#pragma unroll
        for (int e = 0; e < 4; e++) oacc[nt][e] = 0.0f;
    float l0 = 0.0f, l1 = 0.0f;

#pragma unroll 1
    for (int step = 0; step < 64; step++) {
        // issue next step's tiles (double buffer)
        if (step + 1 < 64) {
            int t0n = (step + 1) * 64;
            uint32_t bufn = sb + ((step + 1) & 1) * BUF_B;
#pragma unroll
            for (int c = 0; c < 4; c++) {
                int chunk = tid + c * 128;
                int row = chunk >> 3, c8 = chunk & 7;
                uint32_t dst = bufn + (uint32_t)(row * 144 + c8 * 16);
                cp_async16(dst, Qhi + (size_t)(t0n + row) * DD + c8 * 8);
                cp_async16(dst + TILE_B, Qlo + (size_t)(t0n + row) * DD + c8 * 8);
                cp_async16(dst + 2 * TILE_B, VThi + (size_t)row * SS + t0n + c8 * 8);
                cp_async16(dst + 3 * TILE_B, VTlo + (size_t)row * SS + t0n + c8 * 8);
            }
            CP_COMMIT();
            CP_WAIT(1);
        } else {
            CP_WAIT(0);
        }
        __syncthreads();

        uint32_t buf = sb + (step & 1) * BUF_B;
        uint32_t Qh = buf, Ql = buf + TILE_B;
        uint32_t Vh = buf + 2 * TILE_B, Vl = buf + 3 * TILE_B;

        // ---- MMA1: S(16x64) = K . Q^T; bq loaded once per (kc,p) ----
        float sacc[8][4];
#pragma unroll
        for (int nt = 0; nt < 8; nt++)
#pragma unroll
            for (int e = 0; e < 4; e++) sacc[nt][e] = 0.0f;

#pragma unroll
        for (int kc = 0; kc < 4; kc++) {
#pragma unroll
            for (int p = 0; p < 4; p++) {
                uint32_t bqh[4], bql[4];
                ldsm_x4(bqh, b2_addr_ld(Qh, p * 16, kc * 16, lane, LDP));
                ldsm_x4(bql, b2_addr_ld(Ql, p * 16, kc * 16, lane, LDP));
                mma16816(sacc[2 * p + 0], Khf[kc], bqh + 0);
                mma16816(sacc[2 * p + 1], Khf[kc], bqh + 2);
                mma16816(sacc[2 * p + 0], Khf[kc], bql + 0);
                mma16816(sacc[2 * p + 1], Khf[kc], bql + 2);
                mma16816(sacc[2 * p + 0], Klf[kc], bqh + 0);
                mma16816(sacc[2 * p + 1], Klf[kc], bqh + 2);
            }
        }

        // ---- masked exp (no max subtraction; scores bounded) ----
        const int mbase = step * 64;
#pragma unroll
        for (int nt = 0; nt < 8; nt++) {
            int m0c = msk[mbase + nt * 8 + tig * 2 + 0];
            int m1c = msk[mbase + nt * 8 + tig * 2 + 1];
            float p0 = m0c ? __expf(sacc[nt][0] * 0.125f) : 0.0f;
            float p1 = m1c ? __expf(sacc[nt][1] * 0.125f) : 0.0f;
            float p2 = m0c ? __expf(sacc[nt][2] * 0.125f) : 0.0f;
            float p3 = m1c ? __expf(sacc[nt][3] * 0.125f) : 0.0f;
            sacc[nt][0] = p0; sacc[nt][1] = p1;
            sacc[nt][2] = p2; sacc[nt][3] = p3;
            l0 += p0 + p1;
            l1 += p2 + p3;
        }

        // ---- build P A-fragments hi/lo from accumulators ----
        uint32_t Ph[4][4], Pl[4][4];
#pragma unroll
        for (int kc = 0; kc < 4; kc++) {
            int t0 = 2 * kc, t1 = 2 * kc + 1;
            float h00, l00, h01, l01, h02, l02, h03, l03;
            float h10, l10, h11, l11, h12, l12, h13, l13;
            bsplit(sacc[t0][0], h00, l00); bsplit(sacc[t0][1], h01, l01);
            bsplit(sacc[t0][2], h02, l02); bsplit(sacc[t0][3], h03, l03);
            bsplit(sacc[t1][0], h10, l10); bsplit(sacc[t1][1], h11, l11);
            bsplit(sacc[t1][2], h12, l12); bsplit(sacc[t1][3], h13, l13);
            Ph[kc][0] = pack_bf16x2(h00, h01); Ph[kc][1] = pack_bf16x2(h02, h03);
            Ph[kc][2] = pack_bf16x2(h10, h11); Ph[kc][3] = pack_bf16x2(h12, h13);
            Pl[kc][0] = pack_bf16x2(l00, l01); Pl[kc][1] = pack_bf16x2(l02, l03);
            Pl[kc][2] = pack_bf16x2(l10, l11); Pl[kc][3] = pack_bf16x2(l12, l13);
        }

        // ---- MMA2: O(16x64) += P . V; bv loaded once per (kc,p) ----
#pragma unroll
        for (int kc = 0; kc < 4; kc++) {
#pragma unroll
            for (int p = 0; p < 4; p++) {
                uint32_t bvh[4], bvl[4];
                ldsm_x4(bvh, b2_addr_ld(Vh, p * 16, kc * 16, lane, LDP));
                ldsm_x4(bvl, b2_addr_ld(Vl, p * 16, kc * 16, lane, LDP));
                mma16816(oacc[2 * p + 0], Ph[kc], bvh + 0);
                mma16816(oacc[2 * p + 1], Ph[kc], bvh + 2);
                mma16816(oacc[2 * p + 0], Ph[kc], bvl + 0);
                mma16816(oacc[2 * p + 1], Ph[kc], bvl + 2);
                mma16816(oacc[2 * p + 0], Pl[kc], bvh + 0);
                mma16816(oacc[2 * p + 1], Pl[kc], bvh + 2);
            }
        }
        __syncthreads();   // compute done before this buffer is refilled
    }

    // ---- epilogue: warp-local l reduce, normalize, store ----
    l0 += __shfl_xor_sync(0xffffffffu, l0, 1);
    l0 += __shfl_xor_sync(0xffffffffu, l0, 2);
    l1 += __shfl_xor_sync(0xffffffffu, l1, 1);
    l1 += __shfl_xor_sync(0xffffffffu, l1, 2);
    float inv0 = 1.0f / l0;
    float inv1 = 1.0f / l1;

    int row0 = r0 + wid * 16 + gid;
    int row1 = row0 + 8;
#pragma unroll
    for (int nt = 0; nt < 8; nt++) {
        int d0 = nt * 8 + tig * 2;
        *(float2*)&out[((size_t)b * SS + row0) * DD + d0] =
            make_float2(oacc[nt][0] * inv0, oacc[nt][1] * inv0);
        *(float2*)&out[((size_t)b * SS + row1) * DD + d0] =
            make_float2(oacc[nt][2] * inv1, oacc[nt][3] * inv1);
    }
}

extern "C" void kernel_launch(void* const* d_in, const int* in_sizes, int n_in,
                              void* d_out, int out_size) {
    const float* x    = (const float*)d_in[0];
    const int*   mask = (const int*)d_in[1];
    const float* Wk   = (const float*)d_in[2];
    const float* Wq   = (const float*)d_in[3];
    const float* Wv   = (const float*)d_in[4];
    float* out = (float*)d_out;

    cudaFuncSetAttribute(proj_mma_kernel,
                         cudaFuncAttributeMaxDynamicSharedMemorySize, PSMEM);
    proj_mma_kernel<<<128, 256, PSMEM>>>(x, Wk, Wq, Wv);

    cudaFuncSetAttribute(attn_mma_kernel,
                         cudaFuncAttributeMaxDynamicSharedMemorySize, ASMEM);
    dim3 grid(64, 4);
    attn_mma_kernel<<<grid, 128, ASMEM>>>(mask, out);
}

// round 9
// speedup vs baseline: 4.9836x; 1.5572x over previous
#include <cuda_runtime.h>
#include <cuda_bf16.h>
#include <cuda_fp16.h>
#include <cstdint>

#define BB 4
#define SS 4096
#define HH 1024
#define DD 64

// fp16 projection outputs (written by proj, read by attn)
__device__ __align__(16) __half g_Kh[BB * SS * DD];
__device__ __align__(16) __half g_Qh[BB * SS * DD];
__device__ __align__(16) __half g_VTh[BB * DD * SS];   // transposed [b][d][t]

// ===========================================================================
// Helpers
// ===========================================================================
__device__ __forceinline__ uint32_t smem_u32_of(const void* p) {
    uint32_t addr;
    asm("{ .reg .u64 tmp; cvta.to.shared.u64 tmp, %1; cvt.u32.u64 %0, tmp; }"
        : "=r"(addr) : "l"(p));
    return addr;
}

__device__ __forceinline__ void ldsm_x4(uint32_t* r, uint32_t addr) {
    asm volatile("ldmatrix.sync.aligned.m8n8.x4.shared.b16 {%0,%1,%2,%3}, [%4];"
                 : "=r"(r[0]), "=r"(r[1]), "=r"(r[2]), "=r"(r[3]) : "r"(addr));
}
// bf16 MMA (projection)
__device__ __forceinline__ void mma16816(float* d, const uint32_t* a,
                                         const uint32_t* b) {
    asm volatile(
        "mma.sync.aligned.m16n8k16.row.col.f32.bf16.bf16.f32 "
        "{%0,%1,%2,%3}, {%4,%5,%6,%7}, {%8,%9}, {%0,%1,%2,%3};"
        : "+f"(d[0]), "+f"(d[1]), "+f"(d[2]), "+f"(d[3])
        : "r"(a[0]), "r"(a[1]), "r"(a[2]), "r"(a[3]), "r"(b[0]), "r"(b[1]));
}
// fp16 MMA (attention)
__device__ __forceinline__ void mma16816h(float* d, const uint32_t* a,
                                          const uint32_t* b) {
    asm volatile(
        "mma.sync.aligned.m16n8k16.row.col.f32.f16.f16.f32 "
        "{%0,%1,%2,%3}, {%4,%5,%6,%7}, {%8,%9}, {%0,%1,%2,%3};"
        : "+f"(d[0]), "+f"(d[1]), "+f"(d[2]), "+f"(d[3])
        : "r"(a[0]), "r"(a[1]), "r"(a[2]), "r"(a[3]), "r"(b[0]), "r"(b[1]));
}

__device__ __forceinline__ uint32_t pack_bf16x2(float lo, float hi) {
    __nv_bfloat162 t = __floats2bfloat162_rn(lo, hi);
    return *(uint32_t*)&t;
}
__device__ __forceinline__ uint32_t pack_h2(float lo, float hi) {
    __half2 t = __floats2half2_rn(lo, hi);
    return *(uint32_t*)&t;
}
__device__ __forceinline__ void bsplit(float v, float& h, float& l) {
    __nv_bfloat16 hb = __float2bfloat16(v);
    h = __bfloat162float(hb);
    l = v - h;
}

__device__ __forceinline__ void cp_async16(uint32_t smem_addr, const void* gptr) {
    asm volatile("cp.async.ca.shared.global [%0], [%1], 16;"
                 :: "r"(smem_addr), "l"(gptr) : "memory");
}
#define CP_COMMIT() asm volatile("cp.async.commit_group;" ::: "memory")
#define CP_WAIT(n)  asm volatile("cp.async.wait_group %0;" :: "n"(n) : "memory")

__device__ __forceinline__ uint32_t a_addr_ld(uint32_t base, int row0, int col0,
                                              int lane, int ld) {
    int t = lane >> 3, ri = lane & 7;
    int row = row0 + ri + ((t & 1) << 3);
    int col = col0 + ((t >> 1) << 3);
    return base + (uint32_t)(row * ld + col) * 2;
}
__device__ __forceinline__ uint32_t b2_addr_ld(uint32_t base, int n0, int k0,
                                               int lane, int ld) {
    int row = n0 + ((lane >> 4) << 3) + (lane & 7);
    int col = k0 + (((lane >> 3) & 1) << 3);
    return base + (uint32_t)(row * ld + col) * 2;
}

// ===========================================================================
// Projection: bf16 3-pass split GEMM (internal math unchanged, ~4e-6 err);
// epilogue writes fp16 K, Q (row-major) and V^T (transposed).
// ===========================================================================
#define PLDP 40
#define PX_HI 0
#define PX_LO (PX_HI + 128 * PLDP * 2)
#define PW_HI (PX_LO + 128 * PLDP * 2)
#define PW_LO (PW_HI + 192 * PLDP * 2)
#define PSMEM (PW_LO + 192 * PLDP * 2)

__global__ void __launch_bounds__(256) proj_mma_kernel(const float* __restrict__ x,
                                                       const float* __restrict__ Wk,
                                                       const float* __restrict__ Wq,
                                                       const float* __restrict__ Wv) {
    extern __shared__ char smem[];
    const uint32_t sb = smem_u32_of(smem);

    const int tid = threadIdx.x;
    const int wid = tid >> 5;
    const int lane = tid & 31;
    const int warp_m = wid & 3;
    const int warp_n = wid >> 2;
    const int m0 = blockIdx.x * 128;

    float4 xr[4], wr[6];

#pragma unroll
    for (int j = 0; j < 4; j++) {
        int idx = tid + 256 * j;
        xr[j] = *(const float4*)&x[(size_t)(m0 + (idx >> 3)) * HH + (idx & 7) * 4];
    }
#pragma unroll
    for (int j = 0; j < 6; j++) {
        int idx = tid + 256 * j;
        int row = idx >> 3;
        const float* W = (row < 64) ? Wk : ((row < 128) ? Wq : Wv);
        wr[j] = *(const float4*)&W[(size_t)(row & 63) * HH + (idx & 7) * 4];
    }

    float acc[2][12][4];
#pragma unroll
    for (int mt = 0; mt < 2; mt++)
#pragma unroll
        for (int nn = 0; nn < 12; nn++)
#pragma unroll
            for (int e = 0; e < 4; e++) acc[mt][nn][e] = 0.0f;

#pragma unroll 1
    for (int it = 0; it < 32; it++) {
#pragma unroll
        for (int j = 0; j < 4; j++) {
            int idx = tid + 256 * j;
            int row = idx >> 3, c4 = idx & 7;
            float h0, l0, h1, l1, h2, l2, h3, l3;
            bsplit(xr[j].x, h0, l0); bsplit(xr[j].y, h1, l1);
            bsplit(xr[j].z, h2, l2); bsplit(xr[j].w, h3, l3);
            *(uint2*)(smem + PX_HI + row * PLDP * 2 + c4 * 8) =
                make_uint2(pack_bf16x2(h0, h1), pack_bf16x2(h2, h3));
            *(uint2*)(smem + PX_LO + row * PLDP * 2 + c4 * 8) =
                make_uint2(pack_bf16x2(l0, l1), pack_bf16x2(l2, l3));
        }
#pragma unroll
        for (int j = 0; j < 6; j++) {
            int idx = tid + 256 * j;
            int row = idx >> 3, c4 = idx & 7;
            float h0, l0, h1, l1, h2, l2, h3, l3;
            bsplit(wr[j].x, h0, l0); bsplit(wr[j].y, h1, l1);
            bsplit(wr[j].z, h2, l2); bsplit(wr[j].w, h3, l3);
            *(uint2*)(smem + PW_HI + row * PLDP * 2 + c4 * 8) =
                make_uint2(pack_bf16x2(h0, h1), pack_bf16x2(h2, h3));
            *(uint2*)(smem + PW_LO + row * PLDP * 2 + c4 * 8) =
                make_uint2(pack_bf16x2(l0, l1), pack_bf16x2(l2, l3));
        }
        __syncthreads();

        if (it + 1 < 32) {
            int k0 = (it + 1) * 32;
#pragma unroll
            for (int j = 0; j < 4; j++) {
                int idx = tid + 256 * j;
                xr[j] = *(const float4*)&x[(size_t)(m0 + (idx >> 3)) * HH + k0 + (idx & 7) * 4];
            }
#pragma unroll
            for (int j = 0; j < 6; j++) {
                int idx = tid + 256 * j;
                int row = idx >> 3;
                const float* W = (row < 64) ? Wk : ((row < 128) ? Wq : Wv);
                wr[j] = *(const float4*)&W[(size_t)(row & 63) * HH + k0 + (idx & 7) * 4];
            }
        }

#pragma unroll
        for (int kc = 0; kc < 2; kc++) {
            uint32_t ah[2][4], al[2][4];
#pragma unroll
            for (int mt = 0; mt < 2; mt++) {
                ldsm_x4(ah[mt], a_addr_ld(sb + PX_HI, warp_m * 32 + mt * 16, kc * 16, lane, PLDP));
                ldsm_x4(al[mt], a_addr_ld(sb + PX_LO, warp_m * 32 + mt * 16, kc * 16, lane, PLDP));
            }
#pragma unroll
            for (int nh = 0; nh < 2; nh++) {
                uint32_t bh[6][2], bl[6][2];
#pragma unroll
                for (int pp = 0; pp < 3; pp++) {
                    uint32_t tmp[4];
                    int n0 = warp_n * 96 + nh * 48 + pp * 16;
                    ldsm_x4(tmp, b2_addr_ld(sb + PW_HI, n0, kc * 16, lane, PLDP));
                    bh[2 * pp][0] = tmp[0]; bh[2 * pp][1] = tmp[1];
                    bh[2 * pp + 1][0] = tmp[2]; bh[2 * pp + 1][1] = tmp[3];
                    ldsm_x4(tmp, b2_addr_ld(sb + PW_LO, n0, kc * 16, lane, PLDP));
                    bl[2 * pp][0] = tmp[0]; bl[2 * pp][1] = tmp[1];
                    bl[2 * pp + 1][0] = tmp[2]; bl[2 * pp + 1][1] = tmp[3];
                }
#pragma unroll
                for (int mt = 0; mt < 2; mt++)
#pragma unroll
                    for (int nt = 0; nt < 6; nt++) {
                        float* d = acc[mt][nh * 6 + nt];
                        mma16816(d, ah[mt], bh[nt]);
                        mma16816(d, ah[mt], bl[nt]);
                        mma16816(d, al[mt], bh[nt]);
                    }
            }
        }
        __syncthreads();
    }

    // ---- epilogue: write fp16 K/Q row-major, V transposed ----
#pragma unroll
    for (int mt = 0; mt < 2; mt++)
#pragma unroll
        for (int rp = 0; rp < 2; rp++) {
            int row = m0 + warp_m * 32 + mt * 16 + rp * 8 + (lane >> 2);
            int bb_ = row >> 12, t = row & 4095;
#pragma unroll
            for (int nn = 0; nn < 12; nn++) {
                int n = warp_n * 96 + nn * 8 + (lane & 3) * 2;
                int which = n >> 6, d = n & 63;
                float v0 = acc[mt][nn][rp * 2 + 0];
                float v1 = acc[mt][nn][rp * 2 + 1];
                if (which == 2) {
                    size_t base = (size_t)bb_ * DD * SS;
                    g_VTh[base + (size_t)d * SS + t] = __float2half(v0);
                    g_VTh[base + (size_t)(d + 1) * SS + t] = __float2half(v1);
                } else {
                    __half* Bh = which ? g_Qh : g_Kh;
                    *(uint32_t*)&Bh[(size_t)row * DD + d] = pack_h2(v0, v1);
                }
            }
        }
}

// ===========================================================================
// Attention R9: fp16 single-pass MMAs (3x fewer MMAs), triple-buffered
// cp.async pipeline with ONE __syncthreads per step.
// 128 threads / 4 warps / 64 K-rows per CTA; grid (64,4).
// ===========================================================================
#define LDP 72                              // fp16/row -> 144 B rows
#define TILE_B (64 * LDP * 2)               // 9216 bytes per 64x64 tile
#define BUF_B  (2 * TILE_B)                 // Q, V = 18432
#define AMSK   (3 * BUF_B)                  // 55296
#define ASMEM  (AMSK + SS * 4)              // + 16 KB mask = 71680

__global__ void __launch_bounds__(128, 3) attn_mma_kernel(const int* __restrict__ mask,
                                                          float* __restrict__ out) {
    extern __shared__ char smem[];
    const uint32_t sb = smem_u32_of(smem);

    const int tid = threadIdx.x;
    const int wid = tid >> 5;               // 0..3 -> rows wid*16..+16
    const int lane = tid & 31;
    const int gid = lane >> 2;
    const int tig = lane & 3;
    const int b = blockIdx.y;
    const int r0 = blockIdx.x * 64;

    const __half* Kh = g_Kh + (size_t)b * SS * DD;
    const __half* Qh = g_Qh + (size_t)b * SS * DD;
    const __half* VTh = g_VTh + (size_t)b * DD * SS;

    const int* msk = (const int*)(smem + AMSK);

    // ---- stage K + mask via cp.async (K staged in buf0 region) ----
#pragma unroll
    for (int j = 0; j < 4; j++) {
        int chunk = tid + 128 * j;          // 0..511 (64 rows x 8 chunks)
        int row = chunk >> 3, c8 = chunk & 7;
        cp_async16(sb + (uint32_t)(row * 144 + c8 * 16),
                   Kh + (size_t)(r0 + row) * DD + c8 * 8);
    }
#pragma unroll
    for (int j = 0; j < 8; j++) {
        int chunk = tid + 128 * j;          // 0..1023 (16 KB / 16 B)
        cp_async16(sb + AMSK + chunk * 16, mask + b * SS + chunk * 4);
    }
    CP_COMMIT();
    CP_WAIT(0);
    __syncthreads();

    uint32_t Kf[4][4];
#pragma unroll
    for (int kc = 0; kc < 4; kc++)
        ldsm_x4(Kf[kc], a_addr_ld(sb, wid * 16, kc * 16, lane, LDP));
    __syncthreads();   // K staging area becomes buffer 0

    // ---- prologue: issue steps 0 and 1 ----
#pragma unroll
    for (int s = 0; s < 2; s++) {
        uint32_t bufn = sb + (uint32_t)s * BUF_B;
        int t0n = s * 64;
#pragma unroll
        for (int c = 0; c < 4; c++) {
            int chunk = tid + c * 128;
            int row = chunk >> 3, c8 = chunk & 7;
            uint32_t dst = bufn + (uint32_t)(row * 144 + c8 * 16);
            cp_async16(dst, Qh + (size_t)(t0n + row) * DD + c8 * 8);
            cp_async16(dst + TILE_B, VTh + (size_t)row * SS + t0n + c8 * 8);
        }
        CP_COMMIT();
    }

    float oacc[8][4];
#pragma unroll
    for (int nt = 0; nt < 8; nt++)
#pragma unroll
        for (int e = 0; e < 4; e++) oacc[nt][e] = 0.0f;
    float l0 = 0.0f, l1 = 0.0f;

#pragma unroll 1
    for (int step = 0; step < 64; step++) {
        // own group for this step's buffer done; barrier gives cross-thread
        // visibility AND write-after-read protection for the issue below.
        if (step == 63) { CP_WAIT(0); } else { CP_WAIT(1); }
        __syncthreads();

        uint32_t buf = sb + (uint32_t)(step % 3) * BUF_B;
        uint32_t Qb = buf, Vb = buf + TILE_B;

        // ---- MMA1: S(16x64) = K . Q^T (single-pass fp16) ----
        float sacc[8][4];
#pragma unroll
        for (int nt = 0; nt < 8; nt++)
#pragma unroll
            for (int e = 0; e < 4; e++) sacc[nt][e] = 0.0f;

#pragma unroll
        for (int kc = 0; kc < 4; kc++) {
#pragma unroll
            for (int p = 0; p < 4; p++) {
                uint32_t bq[4];
                ldsm_x4(bq, b2_addr_ld(Qb, p * 16, kc * 16, lane, LDP));
                mma16816h(sacc[2 * p + 0], Kf[kc], bq + 0);
                mma16816h(sacc[2 * p + 1], Kf[kc], bq + 2);
            }
        }

        // ---- masked exp (no max subtraction; scores bounded) ----
        const int mbase = step * 64;
#pragma unroll
        for (int nt = 0; nt < 8; nt++) {
            int m0c = msk[mbase + nt * 8 + tig * 2 + 0];
            int m1c = msk[mbase + nt * 8 + tig * 2 + 1];
            float p0 = m0c ? __expf(sacc[nt][0] * 0.125f) : 0.0f;
            float p1 = m1c ? __expf(sacc[nt][1] * 0.125f) : 0.0f;
            float p2 = m0c ? __expf(sacc[nt][2] * 0.125f) : 0.0f;
            float p3 = m1c ? __expf(sacc[nt][3] * 0.125f) : 0.0f;
            sacc[nt][0] = p0; sacc[nt][1] = p1;
            sacc[nt][2] = p2; sacc[nt][3] = p3;
            l0 += p0 + p1;
            l1 += p2 + p3;
        }

        // ---- pack P accumulators directly into fp16 A-fragments ----
        uint32_t Pf[4][4];
#pragma unroll
        for (int kc = 0; kc < 4; kc++) {
            int t0 = 2 * kc, t1 = 2 * kc + 1;
            Pf[kc][0] = pack_h2(sacc[t0][0], sacc[t0][1]);
            Pf[kc][1] = pack_h2(sacc[t0][2], sacc[t0][3]);
            Pf[kc][2] = pack_h2(sacc[t1][0], sacc[t1][1]);
            Pf[kc][3] = pack_h2(sacc[t1][2], sacc[t1][3]);
        }

        // ---- MMA2: O(16x64) += P . V (single-pass fp16) ----
#pragma unroll
        for (int kc = 0; kc < 4; kc++) {
#pragma unroll
            for (int p = 0; p < 4; p++) {
                uint32_t bv[4];
                ldsm_x4(bv, b2_addr_ld(Vb, p * 16, kc * 16, lane, LDP));
                mma16816h(oacc[2 * p + 0], Pf[kc], bv + 0);
                mma16816h(oacc[2 * p + 1], Pf[kc], bv + 2);
            }
        }

        // ---- issue step+2's tiles (WAR-safe after the top barrier) ----
        if (step + 2 < 64) {
            int t0n = (step + 2) * 64;
            uint32_t bufn = sb + (uint32_t)((step + 2) % 3) * BUF_B;
#pragma unroll
            for (int c = 0; c < 4; c++) {
                int chunk = tid + c * 128;
                int row = chunk >> 3, c8 = chunk & 7;
                uint32_t dst = bufn + (uint32_t)(row * 144 + c8 * 16);
                cp_async16(dst, Qh + (size_t)(t0n + row) * DD + c8 * 8);
                cp_async16(dst + TILE_B, VTh + (size_t)row * SS + t0n + c8 * 8);
            }
            CP_COMMIT();
        }
    }

    // ---- epilogue: warp-local l reduce, normalize, store ----
    l0 += __shfl_xor_sync(0xffffffffu, l0, 1);
    l0 += __shfl_xor_sync(0xffffffffu, l0, 2);
    l1 += __shfl_xor_sync(0xffffffffu, l1, 1);
    l1 += __shfl_xor_sync(0xffffffffu, l1, 2);
    float inv0 = 1.0f / l0;
    float inv1 = 1.0f / l1;

    int row0 = r0 + wid * 16 + gid;
    int row1 = row0 + 8;
#pragma unroll
    for (int nt = 0; nt < 8; nt++) {
        int d0 = nt * 8 + tig * 2;
        *(float2*)&out[((size_t)b * SS + row0) * DD + d0] =
            make_float2(oacc[nt][0] * inv0, oacc[nt][1] * inv0);
        *(float2*)&out[((size_t)b * SS + row1) * DD + d0] =
            make_float2(oacc[nt][2] * inv1, oacc[nt][3] * inv1);
    }
}

extern "C" void kernel_launch(void* const* d_in, const int* in_sizes, int n_in,
                              void* d_out, int out_size) {
    const float* x    = (const float*)d_in[0];
    const int*   mask = (const int*)d_in[1];
    const float* Wk   = (const float*)d_in[2];
    const float* Wq   = (const float*)d_in[3];
    const float* Wv   = (const float*)d_in[4];
    float* out = (float*)d_out;

    cudaFuncSetAttribute(proj_mma_kernel,
                         cudaFuncAttributeMaxDynamicSharedMemorySize, PSMEM);
    proj_mma_kernel<<<128, 256, PSMEM>>>(x, Wk, Wq, Wv);

    cudaFuncSetAttribute(attn_mma_kernel,
                         cudaFuncAttributeMaxDynamicSharedMemorySize, ASMEM);
    dim3 grid(64, 4);
    attn_mma_kernel<<<grid, 128, ASMEM>>>(mask, out);
}

// round 10
// speedup vs baseline: 6.6316x; 1.3307x over previous
#include <cuda_runtime.h>
#include <cuda_bf16.h>
#include <cuda_fp16.h>
#include <cstdint>

#define BB 4
#define SS 4096
#define HH 1024
#define DD 64

// fp16 projection outputs (written by proj, read by attn)
__device__ __align__(16) __half g_Kh[BB * SS * DD];
__device__ __align__(16) __half g_Qh[BB * SS * DD];
__device__ __align__(16) __half g_VTh[BB * DD * SS];   // transposed [b][d][t]

// ===========================================================================
// Helpers
// ===========================================================================
__device__ __forceinline__ uint32_t smem_u32_of(const void* p) {
    uint32_t addr;
    asm("{ .reg .u64 tmp; cvta.to.shared.u64 tmp, %1; cvt.u32.u64 %0, tmp; }"
        : "=r"(addr) : "l"(p));
    return addr;
}

__device__ __forceinline__ void ldsm_x4(uint32_t* r, uint32_t addr) {
    asm volatile("ldmatrix.sync.aligned.m8n8.x4.shared.b16 {%0,%1,%2,%3}, [%4];"
                 : "=r"(r[0]), "=r"(r[1]), "=r"(r[2]), "=r"(r[3]) : "r"(addr));
}
// fp16 MMA
__device__ __forceinline__ void mma16816h(float* d, const uint32_t* a,
                                          const uint32_t* b) {
    asm volatile(
        "mma.sync.aligned.m16n8k16.row.col.f32.f16.f16.f32 "
        "{%0,%1,%2,%3}, {%4,%5,%6,%7}, {%8,%9}, {%0,%1,%2,%3};"
        : "+f"(d[0]), "+f"(d[1]), "+f"(d[2]), "+f"(d[3])
        : "r"(a[0]), "r"(a[1]), "r"(a[2]), "r"(a[3]), "r"(b[0]), "r"(b[1]));
}

__device__ __forceinline__ uint32_t pack_h2(float lo, float hi) {
    __half2 t = __floats2half2_rn(lo, hi);
    return *(uint32_t*)&t;
}

__device__ __forceinline__ void cp_async16(uint32_t smem_addr, const void* gptr) {
    asm volatile("cp.async.ca.shared.global [%0], [%1], 16;"
                 :: "r"(smem_addr), "l"(gptr) : "memory");
}
#define CP_COMMIT() asm volatile("cp.async.commit_group;" ::: "memory")
#define CP_WAIT(n)  asm volatile("cp.async.wait_group %0;" :: "n"(n) : "memory")

__device__ __forceinline__ uint32_t a_addr_ld(uint32_t base, int row0, int col0,
                                              int lane, int ld) {
    int t = lane >> 3, ri = lane & 7;
    int row = row0 + ri + ((t & 1) << 3);
    int col = col0 + ((t >> 1) << 3);
    return base + (uint32_t)(row * ld + col) * 2;
}
__device__ __forceinline__ uint32_t b2_addr_ld(uint32_t base, int n0, int k0,
                                               int lane, int ld) {
    int row = n0 + ((lane >> 4) << 3) + (lane & 7);
    int col = k0 + (((lane >> 3) & 1) << 3);
    return base + (uint32_t)(row * ld + col) * 2;
}

// ===========================================================================
// Projection R10: single-pass fp16 mma.sync.
//   [K;Q;V][m, n] = x[m, :] . W[n, :],  W = [Wk; Wq; Wv] (192 rows)
// CTA: BM=128, BN=192, BK=32. 8 warps 4(M)x2(N), warp tile 32x96. Grid 128.
// Epilogue writes fp16 K/Q row-major + V transposed.
// ===========================================================================
#define PLDP 40
#define PXS 0
#define PWS (PXS + 128 * PLDP * 2)          // 10240
#define PSMEM (PWS + 192 * PLDP * 2)        // 25600 bytes

__global__ void __launch_bounds__(256) proj_mma_kernel(const float* __restrict__ x,
                                                       const float* __restrict__ Wk,
                                                       const float* __restrict__ Wq,
                                                       const float* __restrict__ Wv) {
    extern __shared__ char smem[];
    const uint32_t sb = smem_u32_of(smem);

    const int tid = threadIdx.x;
    const int wid = tid >> 5;
    const int lane = tid & 31;
    const int warp_m = wid & 3;
    const int warp_n = wid >> 2;
    const int m0 = blockIdx.x * 128;

    float4 xr[4], wr[6];

#pragma unroll
    for (int j = 0; j < 4; j++) {
        int idx = tid + 256 * j;
        xr[j] = *(const float4*)&x[(size_t)(m0 + (idx >> 3)) * HH + (idx & 7) * 4];
    }
#pragma unroll
    for (int j = 0; j < 6; j++) {
        int idx = tid + 256 * j;
        int row = idx >> 3;
        const float* W = (row < 64) ? Wk : ((row < 128) ? Wq : Wv);
        wr[j] = *(const float4*)&W[(size_t)(row & 63) * HH + (idx & 7) * 4];
    }

    float acc[2][12][4];
#pragma unroll
    for (int mt = 0; mt < 2; mt++)
#pragma unroll
        for (int nn = 0; nn < 12; nn++)
#pragma unroll
            for (int e = 0; e < 4; e++) acc[mt][nn][e] = 0.0f;

#pragma unroll 1
    for (int it = 0; it < 32; it++) {
        // ---- STS (fp16, single copy) ----
#pragma unroll
        for (int j = 0; j < 4; j++) {
            int idx = tid + 256 * j;
            int row = idx >> 3, c4 = idx & 7;
            *(uint2*)(smem + PXS + row * PLDP * 2 + c4 * 8) =
                make_uint2(pack_h2(xr[j].x, xr[j].y), pack_h2(xr[j].z, xr[j].w));
        }
#pragma unroll
        for (int j = 0; j < 6; j++) {
            int idx = tid + 256 * j;
            int row = idx >> 3, c4 = idx & 7;
            *(uint2*)(smem + PWS + row * PLDP * 2 + c4 * 8) =
                make_uint2(pack_h2(wr[j].x, wr[j].y), pack_h2(wr[j].z, wr[j].w));
        }
        __syncthreads();

        // ---- prefetch next slab (overlaps MMA) ----
        if (it + 1 < 32) {
            int k0 = (it + 1) * 32;
#pragma unroll
            for (int j = 0; j < 4; j++) {
                int idx = tid + 256 * j;
                xr[j] = *(const float4*)&x[(size_t)(m0 + (idx >> 3)) * HH + k0 + (idx & 7) * 4];
            }
#pragma unroll
            for (int j = 0; j < 6; j++) {
                int idx = tid + 256 * j;
                int row = idx >> 3;
                const float* W = (row < 64) ? Wk : ((row < 128) ? Wq : Wv);
                wr[j] = *(const float4*)&W[(size_t)(row & 63) * HH + k0 + (idx & 7) * 4];
            }
        }

        // ---- MMA: single fp16 pass, BK=32 (2 k-chunks) ----
#pragma unroll
        for (int kc = 0; kc < 2; kc++) {
            uint32_t ah[2][4];
#pragma unroll
            for (int mt = 0; mt < 2; mt++)
                ldsm_x4(ah[mt], a_addr_ld(sb + PXS, warp_m * 32 + mt * 16, kc * 16, lane, PLDP));
#pragma unroll
            for (int nh = 0; nh < 2; nh++) {
                uint32_t bh[6][2];
#pragma unroll
                for (int pp = 0; pp < 3; pp++) {
                    uint32_t tmp[4];
                    int n0 = warp_n * 96 + nh * 48 + pp * 16;
                    ldsm_x4(tmp, b2_addr_ld(sb + PWS, n0, kc * 16, lane, PLDP));
                    bh[2 * pp][0] = tmp[0]; bh[2 * pp][1] = tmp[1];
                    bh[2 * pp + 1][0] = tmp[2]; bh[2 * pp + 1][1] = tmp[3];
                }
#pragma unroll
                for (int mt = 0; mt < 2; mt++)
#pragma unroll
                    for (int nt = 0; nt < 6; nt++)
                        mma16816h(acc[mt][nh * 6 + nt], ah[mt], bh[nt]);
            }
        }
        __syncthreads();
    }

    // ---- epilogue: write fp16 K/Q row-major, V transposed ----
#pragma unroll
    for (int mt = 0; mt < 2; mt++)
#pragma unroll
        for (int rp = 0; rp < 2; rp++) {
            int row = m0 + warp_m * 32 + mt * 16 + rp * 8 + (lane >> 2);
            int bb_ = row >> 12, t = row & 4095;
#pragma unroll
            for (int nn = 0; nn < 12; nn++) {
                int n = warp_n * 96 + nn * 8 + (lane & 3) * 2;
                int which = n >> 6, d = n & 63;
                float v0 = acc[mt][nn][rp * 2 + 0];
                float v1 = acc[mt][nn][rp * 2 + 1];
                if (which == 2) {
                    size_t base = (size_t)bb_ * DD * SS;
                    g_VTh[base + (size_t)d * SS + t] = __float2half(v0);
                    g_VTh[base + (size_t)(d + 1) * SS + t] = __float2half(v1);
                } else {
                    __half* Bh = which ? g_Qh : g_Kh;
                    *(uint32_t*)&Bh[(size_t)row * DD + d] = pack_h2(v0, v1);
                }
            }
        }
}

// ===========================================================================
// Attention R10: fp16 single-pass MMAs, triple-buffered cp.async pipeline,
// one __syncthreads per step, explicit buffer rotation (no % in loop).
// 128 threads / 4 warps / 64 K-rows per CTA; grid (64,4).
// ===========================================================================
#define LDP 72                              // fp16/row -> 144 B rows
#define TILE_B (64 * LDP * 2)               // 9216 bytes per 64x64 tile
#define BUF_B  (2 * TILE_B)                 // Q, V = 18432
#define AMSK   (3 * BUF_B)                  // 55296
#define ASMEM  (AMSK + SS * 4)              // + 16 KB mask = 71680

__global__ void __launch_bounds__(128, 3) attn_mma_kernel(const int* __restrict__ mask,
                                                          float* __restrict__ out) {
    extern __shared__ char smem[];
    const uint32_t sb = smem_u32_of(smem);

    const int tid = threadIdx.x;
    const int wid = tid >> 5;               // 0..3 -> rows wid*16..+16
    const int lane = tid & 31;
    const int gid = lane >> 2;
    const int tig = lane & 3;
    const int b = blockIdx.y;
    const int r0 = blockIdx.x * 64;

    const __half* Kh = g_Kh + (size_t)b * SS * DD;
    const __half* Qh = g_Qh + (size_t)b * SS * DD;
    const __half* VTh = g_VTh + (size_t)b * DD * SS;

    const int* msk = (const int*)(smem + AMSK);

    // ---- stage K + mask via cp.async (K staged in buf0 region) ----
#pragma unroll
    for (int j = 0; j < 4; j++) {
        int chunk = tid + 128 * j;          // 0..511
        int row = chunk >> 3, c8 = chunk & 7;
        cp_async16(sb + (uint32_t)(row * 144 + c8 * 16),
                   Kh + (size_t)(r0 + row) * DD + c8 * 8);
    }
#pragma unroll
    for (int j = 0; j < 8; j++) {
        int chunk = tid + 128 * j;          // 0..1023
        cp_async16(sb + AMSK + chunk * 16, mask + b * SS + chunk * 4);
    }
    CP_COMMIT();
    CP_WAIT(0);
    __syncthreads();

    uint32_t Kf[4][4];
#pragma unroll
    for (int kc = 0; kc < 4; kc++)
        ldsm_x4(Kf[kc], a_addr_ld(sb, wid * 16, kc * 16, lane, LDP));
    __syncthreads();   // K staging area becomes buffer 0

    // ---- prologue: issue steps 0 and 1 ----
#pragma unroll
    for (int s = 0; s < 2; s++) {
        uint32_t bufn = sb + (uint32_t)s * BUF_B;
        int t0n = s * 64;
#pragma unroll
        for (int c = 0; c < 4; c++) {
            int chunk = tid + c * 128;
            int row = chunk >> 3, c8 = chunk & 7;
            uint32_t dst = bufn + (uint32_t)(row * 144 + c8 * 16);
            cp_async16(dst, Qh + (size_t)(t0n + row) * DD + c8 * 8);
            cp_async16(dst + TILE_B, VTh + (size_t)row * SS + t0n + c8 * 8);
        }
        CP_COMMIT();
    }

    float oacc[8][4];
#pragma unroll
    for (int nt = 0; nt < 8; nt++)
#pragma unroll
        for (int e = 0; e < 4; e++) oacc[nt][e] = 0.0f;
    float l0 = 0.0f, l1 = 0.0f;

    const uint32_t B0 = sb, B1 = sb + BUF_B, B2 = sb + 2 * BUF_B;

    // One step. buf = this step's buffer; nbuf = buffer for step+2.
    auto do_step = [&](int step, uint32_t buf, uint32_t nbuf) {
        if (step == 63) { CP_WAIT(0); } else { CP_WAIT(1); }
        __syncthreads();

        uint32_t Qb = buf, Vb = buf + TILE_B;

        // MMA1: S(16x64) = K . Q^T (single-pass fp16)
        float sacc[8][4];
#pragma unroll
        for (int nt = 0; nt < 8; nt++)
#pragma unroll
            for (int e = 0; e < 4; e++) sacc[nt][e] = 0.0f;

#pragma unroll
        for (int kc = 0; kc < 4; kc++) {
#pragma unroll
            for (int p = 0; p < 4; p++) {
                uint32_t bq[4];
                ldsm_x4(bq, b2_addr_ld(Qb, p * 16, kc * 16, lane, LDP));
                mma16816h(sacc[2 * p + 0], Kf[kc], bq + 0);
                mma16816h(sacc[2 * p + 1], Kf[kc], bq + 2);
            }
        }

        // masked exp (no max subtraction; scores bounded)
        const int mbase = step * 64;
#pragma unroll
        for (int nt = 0; nt < 8; nt++) {
            int m0c = msk[mbase + nt * 8 + tig * 2 + 0];
            int m1c = msk[mbase + nt * 8 + tig * 2 + 1];
            float p0 = m0c ? __expf(sacc[nt][0] * 0.125f) : 0.0f;
            float p1 = m1c ? __expf(sacc[nt][1] * 0.125f) : 0.0f;
            float p2 = m0c ? __expf(sacc[nt][2] * 0.125f) : 0.0f;
            float p3 = m1c ? __expf(sacc[nt][3] * 0.125f) : 0.0f;
            sacc[nt][0] = p0; sacc[nt][1] = p1;
            sacc[nt][2] = p2; sacc[nt][3] = p3;
            l0 += p0 + p1;
            l1 += p2 + p3;
        }

        // pack P accumulators directly into fp16 A-fragments
        uint32_t Pf[4][4];
#pragma unroll
        for (int kc = 0; kc < 4; kc++) {
            int t0 = 2 * kc, t1 = 2 * kc + 1;
            Pf[kc][0] = pack_h2(sacc[t0][0], sacc[t0][1]);
            Pf[kc][1] = pack_h2(sacc[t0][2], sacc[t0][3]);
            Pf[kc][2] = pack_h2(sacc[t1][0], sacc[t1][1]);
            Pf[kc][3] = pack_h2(sacc[t1][2], sacc[t1][3]);
        }

        // MMA2: O(16x64) += P . V (single-pass fp16)
#pragma unroll
        for (int kc = 0; kc < 4; kc++) {
#pragma unroll
            for (int p = 0; p < 4; p++) {
                uint32_t bv[4];
                ldsm_x4(bv, b2_addr_ld(Vb, p * 16, kc * 16, lane, LDP));
                mma16816h(oacc[2 * p + 0], Pf[kc], bv + 0);
                mma16816h(oacc[2 * p + 1], Pf[kc], bv + 2);
            }
        }

        // issue step+2's tiles into nbuf (WAR-safe after the top barrier)
        if (step + 2 < 64) {
            int t0n = (step + 2) * 64;
#pragma unroll
            for (int c = 0; c < 4; c++) {
                int chunk = tid + c * 128;
                int row = chunk >> 3, c8 = chunk & 7;
                uint32_t dst = nbuf + (uint32_t)(row * 144 + c8 * 16);
                cp_async16(dst, Qh + (size_t)(t0n + row) * DD + c8 * 8);
                cp_async16(dst + TILE_B, VTh + (size_t)row * SS + t0n + c8 * 8);
            }
            CP_COMMIT();
        }
    };

#pragma unroll 1
    for (int s = 0; s < 63; s += 3) {
        do_step(s + 0, B0, B2);
        do_step(s + 1, B1, B0);
        do_step(s + 2, B2, B1);
    }
    do_step(63, B0, B2);

    // ---- epilogue: warp-local l reduce, normalize, store ----
    l0 += __shfl_xor_sync(0xffffffffu, l0, 1);
    l0 += __shfl_xor_sync(0xffffffffu, l0, 2);
    l1 += __shfl_xor_sync(0xffffffffu, l1, 1);
    l1 += __shfl_xor_sync(0xffffffffu, l1, 2);
    float inv0 = 1.0f / l0;
    float inv1 = 1.0f / l1;

    int row0 = r0 + wid * 16 + gid;
    int row1 = row0 + 8;
#pragma unroll
    for (int nt = 0; nt < 8; nt++) {
        int d0 = nt * 8 + tig * 2;
        *(float2*)&out[((size_t)b * SS + row0) * DD + d0] =
            make_float2(oacc[nt][0] * inv0, oacc[nt][1] * inv0);
        *(float2*)&out[((size_t)b * SS + row1) * DD + d0] =
            make_float2(oacc[nt][2] * inv1, oacc[nt][3] * inv1);
    }
}

extern "C" void kernel_launch(void* const* d_in, const int* in_sizes, int n_in,
                              void* d_out, int out_size) {
    const float* x    = (const float*)d_in[0];
    const int*   mask = (const int*)d_in[1];
    const float* Wk   = (const float*)d_in[2];
    const float* Wq   = (const float*)d_in[3];
    const float* Wv   = (const float*)d_in[4];
    float* out = (float*)d_out;

    cudaFuncSetAttribute(proj_mma_kernel,
                         cudaFuncAttributeMaxDynamicSharedMemorySize, PSMEM);
    proj_mma_kernel<<<128, 256, PSMEM>>>(x, Wk, Wq, Wv);

    cudaFuncSetAttribute(attn_mma_kernel,
                         cudaFuncAttributeMaxDynamicSharedMemorySize, ASMEM);
    dim3 grid(64, 4);
    attn_mma_kernel<<<grid, 128, ASMEM>>>(mask, out);
}

// round 11
// speedup vs baseline: 6.9719x; 1.0513x over previous
#include <cuda_runtime.h>
#include <cuda_bf16.h>
#include <cuda_fp16.h>
#include <cstdint>

#define BB 4
#define SS 4096
#define HH 1024
#define DD 64

// fp16 projection outputs (written by proj, read by attn).
// K is pre-scaled by 0.125 (softmax scale folded in).
__device__ __align__(16) __half g_Kh[BB * SS * DD];
__device__ __align__(16) __half g_Qh[BB * SS * DD];
__device__ __align__(16) __half g_VTh[BB * DD * SS];   // transposed [b][d][t]

// ===========================================================================
// Helpers
// ===========================================================================
__device__ __forceinline__ uint32_t smem_u32_of(const void* p) {
    uint32_t addr;
    asm("{ .reg .u64 tmp; cvta.to.shared.u64 tmp, %1; cvt.u32.u64 %0, tmp; }"
        : "=r"(addr) : "l"(p));
    return addr;
}

__device__ __forceinline__ void ldsm_x4(uint32_t* r, uint32_t addr) {
    asm volatile("ldmatrix.sync.aligned.m8n8.x4.shared.b16 {%0,%1,%2,%3}, [%4];"
                 : "=r"(r[0]), "=r"(r[1]), "=r"(r[2]), "=r"(r[3]) : "r"(addr));
}
__device__ __forceinline__ void mma16816h(float* d, const uint32_t* a,
                                          const uint32_t* b) {
    asm volatile(
        "mma.sync.aligned.m16n8k16.row.col.f32.f16.f16.f32 "
        "{%0,%1,%2,%3}, {%4,%5,%6,%7}, {%8,%9}, {%0,%1,%2,%3};"
        : "+f"(d[0]), "+f"(d[1]), "+f"(d[2]), "+f"(d[3])
        : "r"(a[0]), "r"(a[1]), "r"(a[2]), "r"(a[3]), "r"(b[0]), "r"(b[1]));
}

__device__ __forceinline__ uint32_t pack_h2(float lo, float hi) {
    __half2 t = __floats2half2_rn(lo, hi);
    return *(uint32_t*)&t;
}

__device__ __forceinline__ void cp_async16(uint32_t smem_addr, const void* gptr) {
    asm volatile("cp.async.ca.shared.global [%0], [%1], 16;"
                 :: "r"(smem_addr), "l"(gptr) : "memory");
}
#define CP_COMMIT() asm volatile("cp.async.commit_group;" ::: "memory")
#define CP_WAIT(n)  asm volatile("cp.async.wait_group %0;" :: "n"(n) : "memory")

__device__ __forceinline__ uint32_t a_addr_ld(uint32_t base, int row0, int col0,
                                              int lane, int ld) {
    int t = lane >> 3, ri = lane & 7;
    int row = row0 + ri + ((t & 1) << 3);
    int col = col0 + ((t >> 1) << 3);
    return base + (uint32_t)(row * ld + col) * 2;
}
__device__ __forceinline__ uint32_t b2_addr_ld(uint32_t base, int n0, int k0,
                                               int lane, int ld) {
    int row = n0 + ((lane >> 4) << 3) + (lane & 7);
    int col = k0 + (((lane >> 3) & 1) << 3);
    return base + (uint32_t)(row * ld + col) * 2;
}

// ===========================================================================
// Projection: single-pass fp16 mma.sync (unchanged from R10 except K scaled
// by 0.125 in the epilogue).
// ===========================================================================
#define PLDP 40
#define PXS 0
#define PWS (PXS + 128 * PLDP * 2)
#define PSMEM (PWS + 192 * PLDP * 2)

__global__ void __launch_bounds__(256) proj_mma_kernel(const float* __restrict__ x,
                                                       const float* __restrict__ Wk,
                                                       const float* __restrict__ Wq,
                                                       const float* __restrict__ Wv) {
    extern __shared__ char smem[];
    const uint32_t sb = smem_u32_of(smem);

    const int tid = threadIdx.x;
    const int wid = tid >> 5;
    const int lane = tid & 31;
    const int warp_m = wid & 3;
    const int warp_n = wid >> 2;
    const int m0 = blockIdx.x * 128;

    float4 xr[4], wr[6];

#pragma unroll
    for (int j = 0; j < 4; j++) {
        int idx = tid + 256 * j;
        xr[j] = *(const float4*)&x[(size_t)(m0 + (idx >> 3)) * HH + (idx & 7) * 4];
    }
#pragma unroll
    for (int j = 0; j < 6; j++) {
        int idx = tid + 256 * j;
        int row = idx >> 3;
        const float* W = (row < 64) ? Wk : ((row < 128) ? Wq : Wv);
        wr[j] = *(const float4*)&W[(size_t)(row & 63) * HH + (idx & 7) * 4];
    }

    float acc[2][12][4];
#pragma unroll
    for (int mt = 0; mt < 2; mt++)
#pragma unroll
        for (int nn = 0; nn < 12; nn++)
#pragma unroll
            for (int e = 0; e < 4; e++) acc[mt][nn][e] = 0.0f;

#pragma unroll 1
    for (int it = 0; it < 32; it++) {
#pragma unroll
        for (int j = 0; j < 4; j++) {
            int idx = tid + 256 * j;
            int row = idx >> 3, c4 = idx & 7;
            *(uint2*)(smem + PXS + row * PLDP * 2 + c4 * 8) =
                make_uint2(pack_h2(xr[j].x, xr[j].y), pack_h2(xr[j].z, xr[j].w));
        }
#pragma unroll
        for (int j = 0; j < 6; j++) {
            int idx = tid + 256 * j;
            int row = idx >> 3, c4 = idx & 7;
            *(uint2*)(smem + PWS + row * PLDP * 2 + c4 * 8) =
                make_uint2(pack_h2(wr[j].x, wr[j].y), pack_h2(wr[j].z, wr[j].w));
        }
        __syncthreads();

        if (it + 1 < 32) {
            int k0 = (it + 1) * 32;
#pragma unroll
            for (int j = 0; j < 4; j++) {
                int idx = tid + 256 * j;
                xr[j] = *(const float4*)&x[(size_t)(m0 + (idx >> 3)) * HH + k0 + (idx & 7) * 4];
            }
#pragma unroll
            for (int j = 0; j < 6; j++) {
                int idx = tid + 256 * j;
                int row = idx >> 3;
                const float* W = (row < 64) ? Wk : ((row < 128) ? Wq : Wv);
                wr[j] = *(const float4*)&W[(size_t)(row & 63) * HH + k0 + (idx & 7) * 4];
            }
        }

#pragma unroll
        for (int kc = 0; kc < 2; kc++) {
            uint32_t ah[2][4];
#pragma unroll
            for (int mt = 0; mt < 2; mt++)
                ldsm_x4(ah[mt], a_addr_ld(sb + PXS, warp_m * 32 + mt * 16, kc * 16, lane, PLDP));
#pragma unroll
            for (int nh = 0; nh < 2; nh++) {
                uint32_t bh[6][2];
#pragma unroll
                for (int pp = 0; pp < 3; pp++) {
                    uint32_t tmp[4];
                    int n0 = warp_n * 96 + nh * 48 + pp * 16;
                    ldsm_x4(tmp, b2_addr_ld(sb + PWS, n0, kc * 16, lane, PLDP));
                    bh[2 * pp][0] = tmp[0]; bh[2 * pp][1] = tmp[1];
                    bh[2 * pp + 1][0] = tmp[2]; bh[2 * pp + 1][1] = tmp[3];
                }
#pragma unroll
                for (int mt = 0; mt < 2; mt++)
#pragma unroll
                    for (int nt = 0; nt < 6; nt++)
                        mma16816h(acc[mt][nh * 6 + nt], ah[mt], bh[nt]);
            }
        }
        __syncthreads();
    }

    // ---- epilogue: fp16 K (pre-scaled by 1/8) / Q row-major, V transposed ----
#pragma unroll
    for (int mt = 0; mt < 2; mt++)
#pragma unroll
        for (int rp = 0; rp < 2; rp++) {
            int row = m0 + warp_m * 32 + mt * 16 + rp * 8 + (lane >> 2);
            int bb_ = row >> 12, t = row & 4095;
#pragma unroll
            for (int nn = 0; nn < 12; nn++) {
                int n = warp_n * 96 + nn * 8 + (lane & 3) * 2;
                int which = n >> 6, d = n & 63;
                float v0 = acc[mt][nn][rp * 2 + 0];
                float v1 = acc[mt][nn][rp * 2 + 1];
                if (which == 2) {
                    size_t base = (size_t)bb_ * DD * SS;
                    g_VTh[base + (size_t)d * SS + t] = __float2half(v0);
                    g_VTh[base + (size_t)(d + 1) * SS + t] = __float2half(v1);
                } else if (which == 1) {
                    *(uint32_t*)&g_Qh[(size_t)row * DD + d] = pack_h2(v0, v1);
                } else {
                    *(uint32_t*)&g_Kh[(size_t)row * DD + d] =
                        pack_h2(v0 * 0.125f, v1 * 0.125f);
                }
            }
        }
}

// ===========================================================================
// Attention R11: 2(M)x2(N) warp grid — warp owns 32 K-rows x 32-t half.
// B-fragment ldsm traffic halved vs 4Mx1N. fp16 single-pass MMAs,
// triple-buffered cp.async, one barrier per step. Cross-warp-n O/l
// reduction once at the end.
// ===========================================================================
#define LDP 72
#define TILE_B (64 * LDP * 2)               // 9216
#define BUF_B  (2 * TILE_B)                 // 18432
#define AMSK   (3 * BUF_B)                  // 55296
#define ASMEM  (AMSK + SS * 4)              // 71680

__global__ void __launch_bounds__(128, 2) attn_mma_kernel(const int* __restrict__ mask,
                                                          float* __restrict__ out) {
    extern __shared__ char smem[];
    const uint32_t sb = smem_u32_of(smem);

    const int tid = threadIdx.x;
    const int wid = tid >> 5;
    const int lane = tid & 31;
    const int gid = lane >> 2;
    const int tig = lane & 3;
    const int warp_m = wid & 1;             // row half: warp_m*32
    const int warp_n = wid >> 1;            // t half:   warp_n*32
    const int b = blockIdx.y;
    const int r0 = blockIdx.x * 64;

    const __half* Kh = g_Kh + (size_t)b * SS * DD;
    const __half* Qh = g_Qh + (size_t)b * SS * DD;
    const __half* VTh = g_VTh + (size_t)b * DD * SS;

    const int* msk = (const int*)(smem + AMSK);

    // ---- stage K + mask via cp.async ----
#pragma unroll
    for (int j = 0; j < 4; j++) {
        int chunk = tid + 128 * j;
        int row = chunk >> 3, c8 = chunk & 7;
        cp_async16(sb + (uint32_t)(row * 144 + c8 * 16),
                   Kh + (size_t)(r0 + row) * DD + c8 * 8);
    }
#pragma unroll
    for (int j = 0; j < 8; j++) {
        int chunk = tid + 128 * j;
        cp_async16(sb + AMSK + chunk * 16, mask + b * SS + chunk * 4);
    }
    CP_COMMIT();
    CP_WAIT(0);
    __syncthreads();

    // K A-fragments: 32 rows (warp_m half), all 64 k
    uint32_t Kf[2][4][4];
#pragma unroll
    for (int mi = 0; mi < 2; mi++)
#pragma unroll
        for (int kc = 0; kc < 4; kc++)
            ldsm_x4(Kf[mi][kc],
                    a_addr_ld(sb, warp_m * 32 + mi * 16, kc * 16, lane, LDP));
    __syncthreads();   // K staging area becomes buffer 0

    // ---- prologue: issue steps 0 and 1 ----
#pragma unroll
    for (int s = 0; s < 2; s++) {
        uint32_t bufn = sb + (uint32_t)s * BUF_B;
        int t0n = s * 64;
#pragma unroll
        for (int c = 0; c < 4; c++) {
            int chunk = tid + c * 128;
            int row = chunk >> 3, c8 = chunk & 7;
            uint32_t dst = bufn + (uint32_t)(row * 144 + c8 * 16);
            cp_async16(dst, Qh + (size_t)(t0n + row) * DD + c8 * 8);
            cp_async16(dst + TILE_B, VTh + (size_t)row * SS + t0n + c8 * 8);
        }
        CP_COMMIT();
    }

    float oacc[2][8][4];
#pragma unroll
    for (int mi = 0; mi < 2; mi++)
#pragma unroll
        for (int nt = 0; nt < 8; nt++)
#pragma unroll
            for (int e = 0; e < 4; e++) oacc[mi][nt][e] = 0.0f;
    float l_part[4] = {0.0f, 0.0f, 0.0f, 0.0f};

    const uint32_t B0 = sb, B1 = sb + BUF_B, B2 = sb + 2 * BUF_B;
    const int tb = warp_n * 32;             // this warp's t offset in tile

    auto do_step = [&](int step, uint32_t buf, uint32_t nbuf) {
        if (step == 63) { CP_WAIT(0); } else { CP_WAIT(1); }
        __syncthreads();

        uint32_t Qb = buf, Vb = buf + TILE_B;

        // MMA1: S(32 x 32) = K(32x64) . Q_half^T
        float sacc[2][4][4];
#pragma unroll
        for (int mi = 0; mi < 2; mi++)
#pragma unroll
            for (int nj = 0; nj < 4; nj++)
#pragma unroll
                for (int e = 0; e < 4; e++) sacc[mi][nj][e] = 0.0f;

#pragma unroll
        for (int kc = 0; kc < 4; kc++) {
#pragma unroll
            for (int nb = 0; nb < 2; nb++) {
                uint32_t bq[4];
                ldsm_x4(bq, b2_addr_ld(Qb, tb + nb * 16, kc * 16, lane, LDP));
#pragma unroll
                for (int mi = 0; mi < 2; mi++) {
                    mma16816h(sacc[mi][nb * 2 + 0], Kf[mi][kc], bq + 0);
                    mma16816h(sacc[mi][nb * 2 + 1], Kf[mi][kc], bq + 2);
                }
            }
        }

        // masked exp (scale pre-folded into K; no max subtraction)
        const int mbase = step * 64 + tb;
#pragma unroll
        for (int nj = 0; nj < 4; nj++) {
            int m0c = msk[mbase + nj * 8 + tig * 2 + 0];
            int m1c = msk[mbase + nj * 8 + tig * 2 + 1];
#pragma unroll
            for (int mi = 0; mi < 2; mi++) {
                float p0 = m0c ? __expf(sacc[mi][nj][0]) : 0.0f;
                float p1 = m1c ? __expf(sacc[mi][nj][1]) : 0.0f;
                float p2 = m0c ? __expf(sacc[mi][nj][2]) : 0.0f;
                float p3 = m1c ? __expf(sacc[mi][nj][3]) : 0.0f;
                sacc[mi][nj][0] = p0; sacc[mi][nj][1] = p1;
                sacc[mi][nj][2] = p2; sacc[mi][nj][3] = p3;
                l_part[mi * 2 + 0] += p0 + p1;
                l_part[mi * 2 + 1] += p2 + p3;
            }
        }

        // pack P accumulators into fp16 A-fragments (k = t, 2 chunks)
        uint32_t Pf[2][2][4];
#pragma unroll
        for (int mi = 0; mi < 2; mi++)
#pragma unroll
            for (int kt = 0; kt < 2; kt++) {
                int t0 = 2 * kt, t1 = 2 * kt + 1;
                Pf[mi][kt][0] = pack_h2(sacc[mi][t0][0], sacc[mi][t0][1]);
                Pf[mi][kt][1] = pack_h2(sacc[mi][t0][2], sacc[mi][t0][3]);
                Pf[mi][kt][2] = pack_h2(sacc[mi][t1][0], sacc[mi][t1][1]);
                Pf[mi][kt][3] = pack_h2(sacc[mi][t1][2], sacc[mi][t1][3]);
            }

        // MMA2: O(32x64) += P(32x32) . V_half
#pragma unroll
        for (int kt = 0; kt < 2; kt++) {
#pragma unroll
            for (int p = 0; p < 4; p++) {
                uint32_t bv[4];
                ldsm_x4(bv, b2_addr_ld(Vb, p * 16, tb + kt * 16, lane, LDP));
#pragma unroll
                for (int mi = 0; mi < 2; mi++) {
                    mma16816h(oacc[mi][2 * p + 0], Pf[mi][kt], bv + 0);
                    mma16816h(oacc[mi][2 * p + 1], Pf[mi][kt], bv + 2);
                }
            }
        }

        // issue step+2's tiles into nbuf (WAR-safe after the top barrier)
        if (step + 2 < 64) {
            int t0n = (step + 2) * 64;
#pragma unroll
            for (int c = 0; c < 4; c++) {
                int chunk = tid + c * 128;
                int row = chunk >> 3, c8 = chunk & 7;
                uint32_t dst = nbuf + (uint32_t)(row * 144 + c8 * 16);
                cp_async16(dst, Qh + (size_t)(t0n + row) * DD + c8 * 8);
                cp_async16(dst + TILE_B, VTh + (size_t)row * SS + t0n + c8 * 8);
            }
            CP_COMMIT();
        }
    };

#pragma unroll 1
    for (int s = 0; s < 63; s += 3) {
        do_step(s + 0, B0, B2);
        do_step(s + 1, B1, B0);
        do_step(s + 2, B2, B1);
    }
    do_step(63, B0, B2);

    // ---- epilogue: reduce l over tig, exchange O/l across warp_n ----
#pragma unroll
    for (int i = 0; i < 4; i++) {
        l_part[i] += __shfl_xor_sync(0xffffffffu, l_part[i], 1);
        l_part[i] += __shfl_xor_sync(0xffffffffu, l_part[i], 2);
    }

    float* Osh = (float*)smem;                       // 64 x 66 fp32 = 16896 B
    float* l_sh = (float*)(smem + 16896);            // 64 fp32
    __syncthreads();                                  // all MMA2 reads done

    if (warp_n == 1) {
#pragma unroll
        for (int mi = 0; mi < 2; mi++)
#pragma unroll
            for (int rp = 0; rp < 2; rp++) {
                int r = warp_m * 32 + mi * 16 + rp * 8 + gid;
#pragma unroll
                for (int nj = 0; nj < 8; nj++) {
                    Osh[r * 66 + nj * 8 + tig * 2 + 0] = oacc[mi][nj][rp * 2 + 0];
                    Osh[r * 66 + nj * 8 + tig * 2 + 1] = oacc[mi][nj][rp * 2 + 1];
                }
                if (tig == 0) l_sh[r] = l_part[mi * 2 + rp];
            }
    }
    __syncthreads();

    if (warp_n == 0) {
#pragma unroll
        for (int mi = 0; mi < 2; mi++)
#pragma unroll
            for (int rp = 0; rp < 2; rp++) {
                int r = warp_m * 32 + mi * 16 + rp * 8 + gid;
                float inv = 1.0f / (l_part[mi * 2 + rp] + l_sh[r]);
#pragma unroll
                for (int nj = 0; nj < 8; nj++) {
                    float o0 = oacc[mi][nj][rp * 2 + 0] + Osh[r * 66 + nj * 8 + tig * 2 + 0];
                    float o1 = oacc[mi][nj][rp * 2 + 1] + Osh[r * 66 + nj * 8 + tig * 2 + 1];
                    *(float2*)&out[((size_t)b * SS + r0 + r) * DD + nj * 8 + tig * 2] =
                        make_float2(o0 * inv, o1 * inv);
                }
            }
    }
}

extern "C" void kernel_launch(void* const* d_in, const int* in_sizes, int n_in,
                              void* d_out, int out_size) {
    const float* x    = (const float*)d_in[0];
    const int*   mask = (const int*)d_in[1];
    const float* Wk   = (const float*)d_in[2];
    const float* Wq   = (const float*)d_in[3];
    const float* Wv   = (const float*)d_in[4];
    float* out = (float*)d_out;

    cudaFuncSetAttribute(proj_mma_kernel,
                         cudaFuncAttributeMaxDynamicSharedMemorySize, PSMEM);
    proj_mma_kernel<<<128, 256, PSMEM>>>(x, Wk, Wq, Wv);

    cudaFuncSetAttribute(attn_mma_kernel,
                         cudaFuncAttributeMaxDynamicSharedMemorySize, ASMEM);
    dim3 grid(64, 4);
    attn_mma_kernel<<<grid, 128, ASMEM>>>(mask, out);
}

// round 12
// speedup vs baseline: 8.2906x; 1.1891x over previous
#include <cuda_runtime.h>
#include <cuda_bf16.h>
#include <cuda_fp16.h>
#include <cstdint>

#define BB 4
#define SS 4096
#define HH 1024
#define DD 64

// fp16 projection outputs. K is pre-scaled by 0.125*log2(e) so the
// attention kernel computes p = exp2(K.Q) with a single MUFU.
__device__ __align__(16) __half g_Kh[BB * SS * DD];
__device__ __align__(16) __half g_Qh[BB * SS * DD];
__device__ __align__(16) __half g_VTh[BB * DD * SS];   // transposed [b][d][t]

// ===========================================================================
// Helpers
// ===========================================================================
__device__ __forceinline__ uint32_t smem_u32_of(const void* p) {
    uint32_t addr;
    asm("{ .reg .u64 tmp; cvta.to.shared.u64 tmp, %1; cvt.u32.u64 %0, tmp; }"
        : "=r"(addr) : "l"(p));
    return addr;
}

__device__ __forceinline__ void ldsm_x4(uint32_t* r, uint32_t addr) {
    asm volatile("ldmatrix.sync.aligned.m8n8.x4.shared.b16 {%0,%1,%2,%3}, [%4];"
                 : "=r"(r[0]), "=r"(r[1]), "=r"(r[2]), "=r"(r[3]) : "r"(addr));
}
__device__ __forceinline__ void mma16816h(float* d, const uint32_t* a,
                                          const uint32_t* b) {
    asm volatile(
        "mma.sync.aligned.m16n8k16.row.col.f32.f16.f16.f32 "
        "{%0,%1,%2,%3}, {%4,%5,%6,%7}, {%8,%9}, {%0,%1,%2,%3};"
        : "+f"(d[0]), "+f"(d[1]), "+f"(d[2]), "+f"(d[3])
        : "r"(a[0]), "r"(a[1]), "r"(a[2]), "r"(a[3]), "r"(b[0]), "r"(b[1]));
}

__device__ __forceinline__ uint32_t pack_h2(float lo, float hi) {
    __half2 t = __floats2half2_rn(lo, hi);
    return *(uint32_t*)&t;
}

__device__ __forceinline__ void cp_async16(uint32_t smem_addr, const void* gptr) {
    asm volatile("cp.async.ca.shared.global [%0], [%1], 16;"
                 :: "r"(smem_addr), "l"(gptr) : "memory");
}
#define CP_COMMIT() asm volatile("cp.async.commit_group;" ::: "memory")
#define CP_WAIT(n)  asm volatile("cp.async.wait_group %0;" :: "n"(n) : "memory")

__device__ __forceinline__ uint32_t a_addr_ld(uint32_t base, int row0, int col0,
                                              int lane, int ld) {
    int t = lane >> 3, ri = lane & 7;
    int row = row0 + ri + ((t & 1) << 3);
    int col = col0 + ((t >> 1) << 3);
    return base + (uint32_t)(row * ld + col) * 2;
}
__device__ __forceinline__ uint32_t b2_addr_ld(uint32_t base, int n0, int k0,
                                               int lane, int ld) {
    int row = n0 + ((lane >> 4) << 3) + (lane & 7);
    int col = k0 + (((lane >> 3) & 1) << 3);
    return base + (uint32_t)(row * ld + col) * 2;
}

// ===========================================================================
// Projection: single-pass fp16 mma.sync (K scaled by 0.125*log2e in epilogue)
// ===========================================================================
#define PLDP 40
#define PXS 0
#define PWS (PXS + 128 * PLDP * 2)
#define PSMEM (PWS + 192 * PLDP * 2)

__global__ void __launch_bounds__(256) proj_mma_kernel(const float* __restrict__ x,
                                                       const float* __restrict__ Wk,
                                                       const float* __restrict__ Wq,
                                                       const float* __restrict__ Wv) {
    extern __shared__ char smem[];
    const uint32_t sb = smem_u32_of(smem);

    const int tid = threadIdx.x;
    const int wid = tid >> 5;
    const int lane = tid & 31;
    const int warp_m = wid & 3;
    const int warp_n = wid >> 2;
    const int m0 = blockIdx.x * 128;

    float4 xr[4], wr[6];

#pragma unroll
    for (int j = 0; j < 4; j++) {
        int idx = tid + 256 * j;
        xr[j] = *(const float4*)&x[(size_t)(m0 + (idx >> 3)) * HH + (idx & 7) * 4];
    }
#pragma unroll
    for (int j = 0; j < 6; j++) {
        int idx = tid + 256 * j;
        int row = idx >> 3;
        const float* W = (row < 64) ? Wk : ((row < 128) ? Wq : Wv);
        wr[j] = *(const float4*)&W[(size_t)(row & 63) * HH + (idx & 7) * 4];
    }

    float acc[2][12][4];
#pragma unroll
    for (int mt = 0; mt < 2; mt++)
#pragma unroll
        for (int nn = 0; nn < 12; nn++)
#pragma unroll
            for (int e = 0; e < 4; e++) acc[mt][nn][e] = 0.0f;

#pragma unroll 1
    for (int it = 0; it < 32; it++) {
#pragma unroll
        for (int j = 0; j < 4; j++) {
            int idx = tid + 256 * j;
            int row = idx >> 3, c4 = idx & 7;
            *(uint2*)(smem + PXS + row * PLDP * 2 + c4 * 8) =
                make_uint2(pack_h2(xr[j].x, xr[j].y), pack_h2(xr[j].z, xr[j].w));
        }
#pragma unroll
        for (int j = 0; j < 6; j++) {
            int idx = tid + 256 * j;
            int row = idx >> 3, c4 = idx & 7;
            *(uint2*)(smem + PWS + row * PLDP * 2 + c4 * 8) =
                make_uint2(pack_h2(wr[j].x, wr[j].y), pack_h2(wr[j].z, wr[j].w));
        }
        __syncthreads();

        if (it + 1 < 32) {
            int k0 = (it + 1) * 32;
#pragma unroll
            for (int j = 0; j < 4; j++) {
                int idx = tid + 256 * j;
                xr[j] = *(const float4*)&x[(size_t)(m0 + (idx >> 3)) * HH + k0 + (idx & 7) * 4];
            }
#pragma unroll
            for (int j = 0; j < 6; j++) {
                int idx = tid + 256 * j;
                int row = idx >> 3;
                const float* W = (row < 64) ? Wk : ((row < 128) ? Wq : Wv);
                wr[j] = *(const float4*)&W[(size_t)(row & 63) * HH + k0 + (idx & 7) * 4];
            }
        }

#pragma unroll
        for (int kc = 0; kc < 2; kc++) {
            uint32_t ah[2][4];
#pragma unroll
            for (int mt = 0; mt < 2; mt++)
                ldsm_x4(ah[mt], a_addr_ld(sb + PXS, warp_m * 32 + mt * 16, kc * 16, lane, PLDP));
#pragma unroll
            for (int nh = 0; nh < 2; nh++) {
                uint32_t bh[6][2];
#pragma unroll
                for (int pp = 0; pp < 3; pp++) {
                    uint32_t tmp[4];
                    int n0 = warp_n * 96 + nh * 48 + pp * 16;
                    ldsm_x4(tmp, b2_addr_ld(sb + PWS, n0, kc * 16, lane, PLDP));
                    bh[2 * pp][0] = tmp[0]; bh[2 * pp][1] = tmp[1];
                    bh[2 * pp + 1][0] = tmp[2]; bh[2 * pp + 1][1] = tmp[3];
                }
#pragma unroll
                for (int mt = 0; mt < 2; mt++)
#pragma unroll
                    for (int nt = 0; nt < 6; nt++)
                        mma16816h(acc[mt][nh * 6 + nt], ah[mt], bh[nt]);
            }
        }
        __syncthreads();
    }

    // ---- epilogue ----
    const float KSC = 0.125f * 1.44269504f;   // fold softmax scale + log2(e)
#pragma unroll
    for (int mt = 0; mt < 2; mt++)
#pragma unroll
        for (int rp = 0; rp < 2; rp++) {
            int row = m0 + warp_m * 32 + mt * 16 + rp * 8 + (lane >> 2);
            int bb_ = row >> 12, t = row & 4095;
#pragma unroll
            for (int nn = 0; nn < 12; nn++) {
                int n = warp_n * 96 + nn * 8 + (lane & 3) * 2;
                int which = n >> 6, d = n & 63;
                float v0 = acc[mt][nn][rp * 2 + 0];
                float v1 = acc[mt][nn][rp * 2 + 1];
                if (which == 2) {
                    size_t base = (size_t)bb_ * DD * SS;
                    g_VTh[base + (size_t)d * SS + t] = __float2half(v0);
                    g_VTh[base + (size_t)(d + 1) * SS + t] = __float2half(v1);
                } else if (which == 1) {
                    *(uint32_t*)&g_Qh[(size_t)row * DD + d] = pack_h2(v0, v1);
                } else {
                    *(uint32_t*)&g_Kh[(size_t)row * DD + d] =
                        pack_h2(v0 * KSC, v1 * KSC);
                }
            }
        }
}

// ===========================================================================
// Attention R12: 128-t double-buffered steps, two 64-t sub-chunks per
// barrier (MMA2 of sub0 overlaps MMA1 of sub1). exp2-based softmax with
// float mask multiplies. 2(M)x2(N) warp grid, K frags register-resident.
// ===========================================================================
#define LDP 72                              // Q rows: 64 d + pad
#define LDP2 136                            // V rows: 128 t + pad
#define QT_B (128 * LDP * 2)                // 18432
#define VT_B (64 * LDP2 * 2)                // 17408
#define BUF2_B (QT_B + VT_B)                // 35840
#define AMSK (2 * BUF2_B)                   // 71680
#define ASMEM (AMSK + SS * 4)               // 88064

__global__ void __launch_bounds__(128, 2) attn_mma_kernel(const int* __restrict__ mask,
                                                          float* __restrict__ out) {
    extern __shared__ char smem[];
    const uint32_t sb = smem_u32_of(smem);

    const int tid = threadIdx.x;
    const int wid = tid >> 5;
    const int lane = tid & 31;
    const int gid = lane >> 2;
    const int tig = lane & 3;
    const int warp_m = wid & 1;             // row half: warp_m*32
    const int warp_n = wid >> 1;            // t half within sub-chunk
    const int b = blockIdx.y;
    const int r0 = blockIdx.x * 64;

    const __half* Kh = g_Kh + (size_t)b * SS * DD;
    const __half* Qh = g_Qh + (size_t)b * SS * DD;
    const __half* VTh = g_VTh + (size_t)b * DD * SS;

    float* msk = (float*)(smem + AMSK);

    // ---- stage K + mask via cp.async ----
#pragma unroll
    for (int j = 0; j < 4; j++) {
        int chunk = tid + 128 * j;          // 0..511
        int row = chunk >> 3, c8 = chunk & 7;
        cp_async16(sb + (uint32_t)(row * 144 + c8 * 16),
                   Kh + (size_t)(r0 + row) * DD + c8 * 8);
    }
#pragma unroll
    for (int j = 0; j < 8; j++) {
        int chunk = tid + 128 * j;          // 0..1023
        cp_async16(sb + AMSK + chunk * 16, mask + b * SS + chunk * 4);
    }
    CP_COMMIT();
    CP_WAIT(0);
    __syncthreads();

    // K A-fragments: 32 rows (warp_m half), all 64 k
    uint32_t Kf[2][4][4];
#pragma unroll
    for (int mi = 0; mi < 2; mi++)
#pragma unroll
        for (int kc = 0; kc < 4; kc++)
            ldsm_x4(Kf[mi][kc],
                    a_addr_ld(sb, warp_m * 32 + mi * 16, kc * 16, lane, LDP));

    // convert mask int -> float in place (each thread owns its elements)
#pragma unroll
    for (int j = 0; j < 32; j++) {
        int idx = tid + 128 * j;
        msk[idx] = (float)((int*)msk)[idx];
    }
    __syncthreads();   // K staging area becomes buffer 0; mask visible

    // ---- prologue: issue step-0 buffer (128 t) ----
#pragma unroll
    for (int j = 0; j < 8; j++) {
        int chunk = tid + 128 * j;          // Q: 1024 chunks
        int row = chunk >> 3, c8 = chunk & 7;
        cp_async16(sb + (uint32_t)(row * 144 + c8 * 16),
                   Qh + (size_t)row * DD + c8 * 8);
    }
#pragma unroll
    for (int j = 0; j < 8; j++) {
        int chunk = tid + 128 * j;          // V: 1024 chunks
        int row = chunk >> 4, c16 = chunk & 15;
        cp_async16(sb + QT_B + (uint32_t)(row * 272 + c16 * 16),
                   VTh + (size_t)row * SS + c16 * 8);
    }
    CP_COMMIT();

    float oacc[2][8][4];
#pragma unroll
    for (int mi = 0; mi < 2; mi++)
#pragma unroll
        for (int nt = 0; nt < 8; nt++)
#pragma unroll
            for (int e = 0; e < 4; e++) oacc[mi][nt][e] = 0.0f;
    float l_part[4] = {0.0f, 0.0f, 0.0f, 0.0f};

    // one 64-t sub-chunk at t-offset tb within the buffer
    auto do_sub = [&](uint32_t Qb, uint32_t Vb, int tb, int mglob) {
        // MMA1: S(32x32) = K . Q_half^T
        float sacc[2][4][4];
#pragma unroll
        for (int mi = 0; mi < 2; mi++)
#pragma unroll
            for (int nj = 0; nj < 4; nj++)
#pragma unroll
                for (int e = 0; e < 4; e++) sacc[mi][nj][e] = 0.0f;

#pragma unroll
        for (int kc = 0; kc < 4; kc++) {
#pragma unroll
            for (int nb = 0; nb < 2; nb++) {
                uint32_t bq[4];
                ldsm_x4(bq, b2_addr_ld(Qb, tb + nb * 16, kc * 16, lane, LDP));
#pragma unroll
                for (int mi = 0; mi < 2; mi++) {
                    mma16816h(sacc[mi][nb * 2 + 0], Kf[mi][kc], bq + 0);
                    mma16816h(sacc[mi][nb * 2 + 1], Kf[mi][kc], bq + 2);
                }
            }
        }

        // p = mask * exp2(s)   (scale+log2e folded into K)
#pragma unroll
        for (int nj = 0; nj < 4; nj++) {
            float mf0 = msk[mglob + nj * 8 + tig * 2 + 0];
            float mf1 = msk[mglob + nj * 8 + tig * 2 + 1];
#pragma unroll
            for (int mi = 0; mi < 2; mi++) {
                float p0 = mf0 * exp2f(sacc[mi][nj][0]);
                float p1 = mf1 * exp2f(sacc[mi][nj][1]);
                float p2 = mf0 * exp2f(sacc[mi][nj][2]);
                float p3 = mf1 * exp2f(sacc[mi][nj][3]);
                sacc[mi][nj][0] = p0; sacc[mi][nj][1] = p1;
                sacc[mi][nj][2] = p2; sacc[mi][nj][3] = p3;
                l_part[mi * 2 + 0] += p0 + p1;
                l_part[mi * 2 + 1] += p2 + p3;
            }
        }

        // pack P into fp16 A-fragments
        uint32_t Pf[2][2][4];
#pragma unroll
        for (int mi = 0; mi < 2; mi++)
#pragma unroll
            for (int kt = 0; kt < 2; kt++) {
                int t0 = 2 * kt, t1 = 2 * kt + 1;
                Pf[mi][kt][0] = pack_h2(sacc[mi][t0][0], sacc[mi][t0][1]);
                Pf[mi][kt][1] = pack_h2(sacc[mi][t0][2], sacc[mi][t0][3]);
                Pf[mi][kt][2] = pack_h2(sacc[mi][t1][0], sacc[mi][t1][1]);
                Pf[mi][kt][3] = pack_h2(sacc[mi][t1][2], sacc[mi][t1][3]);
            }

        // MMA2: O += P . V_half
#pragma unroll
        for (int kt = 0; kt < 2; kt++) {
#pragma unroll
            for (int p = 0; p < 4; p++) {
                uint32_t bv[4];
                ldsm_x4(bv, b2_addr_ld(Vb, p * 16, tb + kt * 16, lane, LDP2));
#pragma unroll
                for (int mi = 0; mi < 2; mi++) {
                    mma16816h(oacc[mi][2 * p + 0], Pf[mi][kt], bv + 0);
                    mma16816h(oacc[mi][2 * p + 1], Pf[mi][kt], bv + 2);
                }
            }
        }
    };

#pragma unroll 1
    for (int step = 0; step < 32; step++) {
        CP_WAIT(0);
        __syncthreads();

        // issue next buffer (its prior readers all passed the barrier)
        if (step + 1 < 32) {
            int t0n = (step + 1) * 128;
            uint32_t bufn = sb + (uint32_t)((step + 1) & 1) * BUF2_B;
#pragma unroll
            for (int j = 0; j < 8; j++) {
                int chunk = tid + 128 * j;
                int row = chunk >> 3, c8 = chunk & 7;
                cp_async16(bufn + (uint32_t)(row * 144 + c8 * 16),
                           Qh + (size_t)(t0n + row) * DD + c8 * 8);
            }
#pragma unroll
            for (int j = 0; j < 8; j++) {
                int chunk = tid + 128 * j;
                int row = chunk >> 4, c16 = chunk & 15;
                cp_async16(bufn + QT_B + (uint32_t)(row * 272 + c16 * 16),
                           VTh + (size_t)row * SS + t0n + c16 * 8);
            }
            CP_COMMIT();
        }

        uint32_t buf = sb + (uint32_t)(step & 1) * BUF2_B;
        uint32_t Qb = buf, Vb = buf + QT_B;
        int mg = step * 128 + warp_n * 32;

        do_sub(Qb, Vb, warp_n * 32, mg);                 // sub-chunk 0
        do_sub(Qb, Vb, 64 + warp_n * 32, mg + 64);       // sub-chunk 1
    }

    // ---- epilogue: reduce l over tig, exchange O/l across warp_n ----
#pragma unroll
    for (int i = 0; i < 4; i++) {
        l_part[i] += __shfl_xor_sync(0xffffffffu, l_part[i], 1);
        l_part[i] += __shfl_xor_sync(0xffffffffu, l_part[i], 2);
    }

    float* Osh = (float*)smem;                       // 64 x 66 fp32
    float* l_sh = (float*)(smem + 16896);            // 64 fp32
    __syncthreads();

    if (warp_n == 1) {
#pragma unroll
        for (int mi = 0; mi < 2; mi++)
#pragma unroll
            for (int rp = 0; rp < 2; rp++) {
                int r = warp_m * 32 + mi * 16 + rp * 8 + gid;
#pragma unroll
                for (int nj = 0; nj < 8; nj++) {
                    Osh[r * 66 + nj * 8 + tig * 2 + 0] = oacc[mi][nj][rp * 2 + 0];
                    Osh[r * 66 + nj * 8 + tig * 2 + 1] = oacc[mi][nj][rp * 2 + 1];
                }
                if (tig == 0) l_sh[r] = l_part[mi * 2 + rp];
            }
    }
    __syncthreads();

    if (warp_n == 0) {
#pragma unroll
        for (int mi = 0; mi < 2; mi++)
#pragma unroll
            for (int rp = 0; rp < 2; rp++) {
                int r = warp_m * 32 + mi * 16 + rp * 8 + gid;
                float inv = 1.0f / (l_part[mi * 2 + rp] + l_sh[r]);
#pragma unroll
                for (int nj = 0; nj < 8; nj++) {
                    float o0 = oacc[mi][nj][rp * 2 + 0] + Osh[r * 66 + nj * 8 + tig * 2 + 0];
                    float o1 = oacc[mi][nj][rp * 2 + 1] + Osh[r * 66 + nj * 8 + tig * 2 + 1];
                    *(float2*)&out[((size_t)b * SS + r0 + r) * DD + nj * 8 + tig * 2] =
                        make_float2(o0 * inv, o1 * inv);
                }
            }
    }
}

extern "C" void kernel_launch(void* const* d_in, const int* in_sizes, int n_in,
                              void* d_out, int out_size) {
    const float* x    = (const float*)d_in[0];
    const int*   mask = (const int*)d_in[1];
    const float* Wk   = (const float*)d_in[2];
    const float* Wq   = (const float*)d_in[3];
    const float* Wv   = (const float*)d_in[4];
    float* out = (float*)d_out;

    cudaFuncSetAttribute(proj_mma_kernel,
                         cudaFuncAttributeMaxDynamicSharedMemorySize, PSMEM);
    proj_mma_kernel<<<128, 256, PSMEM>>>(x, Wk, Wq, Wv);

    cudaFuncSetAttribute(attn_mma_kernel,
                         cudaFuncAttributeMaxDynamicSharedMemorySize, ASMEM);
    dim3 grid(64, 4);
    attn_mma_kernel<<<grid, 128, ASMEM>>>(mask, out);
}